// round 3
// baseline (speedup 1.0000x reference)
#include <cuda_runtime.h>
#include <cstdint>
#include <math.h>

#define Bv 64
#define Tv 256
#define Hv 1024
#define Ev 512
#define Av 512
#define Gv 4096   /* 4*H */
#define Cv 2
#define SCAN_BLOCKS 128

// ---------------- scratch (static device globals; no allocations) ----------------
__device__ float g_embT[(size_t)Tv * Bv * Ev];   // [t*B+b][E]
__device__ float g_xp  [(size_t)Tv * Bv * Gv];   // [t*B+b][4H] (reused both layers)
__device__ float g_seq0[(size_t)Tv * Bv * Hv];
__device__ float g_seq1[(size_t)Tv * Bv * Hv];
__device__ float g_h   [Bv * Hv];
__device__ float g_c   [Bv * Hv];
__device__ float g_m1  [(size_t)Tv * Bv * Av];
__device__ float g_m2  [Bv * Av];
__device__ float g_sc  [Tv * Bv];
__device__ float g_cat [Bv * 2 * Hv];
__device__ float g_nvec[Bv * Hv];
__device__ unsigned g_barrier;

// ---------------- packed f32x2 FMA (sm_103a FFMA2, PTX-only) ----------------
union f2u { float2 f; unsigned long long u; };
__device__ __forceinline__ float2 ffma2(float2 a, float2 b, float2 c) {
    f2u A, B, C, D; A.f = a; B.f = b; C.f = c;
    asm("fma.rn.f32x2 %0, %1, %2, %3;" : "=l"(D.u) : "l"(A.u), "l"(B.u), "l"(C.u));
    return D.f;
}

__device__ __forceinline__ float sigmoidf_(float x) { return 1.f / (1.f + expf(-x)); }

// ---------------- generic tiled SGEMM: C[m][n] = sum_k A[m][k]*B[n][k] (+bias) ----------------
#define BKt 16
__global__ __launch_bounds__(128) void sgemm(
    const float* __restrict__ A, int lda,
    const float* __restrict__ B, int ldb,
    float* __restrict__ C, int ldc,
    int K, const float* __restrict__ bias1, const float* __restrict__ bias2,
    int act)
{
    __shared__ __align__(16) float As[BKt][64 + 4];
    __shared__ __align__(16) float Bs[BKt][64 + 4];
    const int tid = threadIdx.x;
    const int nBase = blockIdx.x * 64;
    const long long mBase = (long long)blockIdx.y * 64;

    const int ty = tid >> 4;   // 0..7
    const int tx = tid & 15;   // 0..15

    float2 acc[8][2];
#pragma unroll
    for (int i = 0; i < 8; i++) { acc[i][0] = make_float2(0.f, 0.f); acc[i][1] = make_float2(0.f, 0.f); }

    for (int k0 = 0; k0 < K; k0 += BKt) {
#pragma unroll
        for (int i = 0; i < 2; i++) {
            int f = i * 128 + tid;
            int m = f >> 2;
            int kq = f & 3;
            float4 va = *(const float4*)&A[(mBase + m) * (long long)lda + k0 + kq * 4];
            As[kq * 4 + 0][m] = va.x; As[kq * 4 + 1][m] = va.y;
            As[kq * 4 + 2][m] = va.z; As[kq * 4 + 3][m] = va.w;
            float4 vb = *(const float4*)&B[(long long)(nBase + m) * ldb + k0 + kq * 4];
            Bs[kq * 4 + 0][m] = vb.x; Bs[kq * 4 + 1][m] = vb.y;
            Bs[kq * 4 + 2][m] = vb.z; Bs[kq * 4 + 3][m] = vb.w;
        }
        __syncthreads();
#pragma unroll
        for (int kk = 0; kk < BKt; kk++) {
            float4 a0 = *(const float4*)&As[kk][ty * 8];
            float4 a1 = *(const float4*)&As[kk][ty * 8 + 4];
            float4 b4 = *(const float4*)&Bs[kk][tx * 4];
            float2 b01 = make_float2(b4.x, b4.y);
            float2 b23 = make_float2(b4.z, b4.w);
            float av[8] = {a0.x, a0.y, a0.z, a0.w, a1.x, a1.y, a1.z, a1.w};
#pragma unroll
            for (int i = 0; i < 8; i++) {
                float2 ad = make_float2(av[i], av[i]);
                acc[i][0] = ffma2(ad, b01, acc[i][0]);
                acc[i][1] = ffma2(ad, b23, acc[i][1]);
            }
        }
        __syncthreads();
    }

    float4 bb = make_float4(0.f, 0.f, 0.f, 0.f);
    if (bias1) bb = *(const float4*)&bias1[nBase + tx * 4];
    if (bias2) {
        float4 b2v = *(const float4*)&bias2[nBase + tx * 4];
        bb.x += b2v.x; bb.y += b2v.y; bb.z += b2v.z; bb.w += b2v.w;
    }
#pragma unroll
    for (int i = 0; i < 8; i++) {
        long long m = mBase + ty * 8 + i;
        float4 r = make_float4(acc[i][0].x + bb.x, acc[i][0].y + bb.y,
                               acc[i][1].x + bb.z, acc[i][1].y + bb.w);
        if (act == 1) { r.x = tanhf(r.x); r.y = tanhf(r.y); r.z = tanhf(r.z); r.w = tanhf(r.w); }
        *(float4*)&C[m * (long long)ldc + nBase + tx * 4] = r;
    }
}

// ---------------- persistent LSTM scan: all 256 steps in ONE kernel ----------------
// 128 blocks x 128 threads. Block n owns hidden units u0=n*8 .. u0+7 and all 4
// gate rows for them (32 W rows). Per step: 64x32x1024 GEMM (FFMA2), fused
// pointwise, one software grid barrier.
__global__ __launch_bounds__(128) void lstm_scan(
    const float* __restrict__ W,    // w_hh [4096][1024]
    const float* __restrict__ xp,   // [T*B][4096], biases folded
    float* __restrict__ seq)        // [T*B][1024]
{
    __shared__ __align__(16) float As[16][64 + 4];   // h chunk, [k][b]
    __shared__ __align__(16) float Bs[16][36];       // W chunk, [k][o]
    __shared__ __align__(16) float Cs[64][36];       // gates+xp staged

    const int tid = threadIdx.x;
    const int u0 = blockIdx.x * 8;
    const int tx = tid & 15;        // output pair: o = 2*tx, 2*tx+1
    const int ty = tid >> 4;        // batch group of 8

    // W row for local output o: g = o>>3, j = o&7 -> row = g*1024 + u0 + j
    const int oB = tid >> 2;                 // 0..31 (for W loads)
    const int kqB = tid & 3;
    const long long wrowB = (long long)((oB >> 3) * Hv + u0 + (oB & 7)) * Hv;

    // xp rows for this thread's two outputs (same gate, adjacent)
    const int o2 = 2 * tx;
    const int growx = (o2 >> 3) * Hv + u0 + (o2 & 7);

    for (int t = 0; t < Tv; t++) {
        float2 acc[8];
#pragma unroll
        for (int i = 0; i < 8; i++) acc[i] = make_float2(0.f, 0.f);

        for (int k0 = 0; k0 < Hv; k0 += 16) {
            // stage h[64][16] transposed (L2-coherent loads: h written by other blocks)
#pragma unroll
            for (int i = 0; i < 2; i++) {
                int f = i * 128 + tid;
                int b = f >> 2;
                int kq = f & 3;
                const float4* hp = (const float4*)&g_h[b * Hv + k0 + kq * 4];
                float4 va = __ldcg(hp);
                As[kq * 4 + 0][b] = va.x; As[kq * 4 + 1][b] = va.y;
                As[kq * 4 + 2][b] = va.z; As[kq * 4 + 3][b] = va.w;
            }
            // stage W[32][16] transposed (stable across steps -> L1-resident)
            {
                float4 vb = *(const float4*)&W[wrowB + k0 + kqB * 4];
                Bs[kqB * 4 + 0][oB] = vb.x; Bs[kqB * 4 + 1][oB] = vb.y;
                Bs[kqB * 4 + 2][oB] = vb.z; Bs[kqB * 4 + 3][oB] = vb.w;
            }
            __syncthreads();
#pragma unroll
            for (int kk = 0; kk < 16; kk++) {
                float4 a0 = *(const float4*)&As[kk][ty * 8];
                float4 a1 = *(const float4*)&As[kk][ty * 8 + 4];
                float2 bp = *(const float2*)&Bs[kk][tx * 2];
                float av[8] = {a0.x, a0.y, a0.z, a0.w, a1.x, a1.y, a1.z, a1.w};
#pragma unroll
                for (int i = 0; i < 8; i++)
                    acc[i] = ffma2(make_float2(av[i], av[i]), bp, acc[i]);
            }
            __syncthreads();
        }

        // stage gates + xp into Cs
#pragma unroll
        for (int i = 0; i < 8; i++) {
            int b = ty * 8 + i;
            float2 xv = *(const float2*)&xp[((size_t)(t * Bv + b)) * Gv + growx];
            Cs[b][o2]     = acc[i].x + xv.x;
            Cs[b][o2 + 1] = acc[i].y + xv.y;
        }
        __syncthreads();

        // fused pointwise: 512 (b,j) pairs, 4 per thread
#pragma unroll
        for (int q = 0; q < 4; q++) {
            int p = tid + q * 128;
            int b = p >> 3;
            int j = p & 7;
            float gi = Cs[b][j];
            float gf = Cs[b][8 + j];
            float gg = Cs[b][16 + j];
            float go = Cs[b][24 + j];
            int idx = b * Hv + u0 + j;
            float c = sigmoidf_(gf) * g_c[idx] + sigmoidf_(gi) * tanhf(gg);
            float h = sigmoidf_(go) * tanhf(c);
            g_c[idx] = c;
            g_h[idx] = h;
            seq[((size_t)(t * Bv + b)) * Hv + u0 + j] = h;
        }

        // grid barrier (fence-based release/acquire), skipped after last step
        if (t < Tv - 1) {
            __threadfence();
            __syncthreads();
            if (tid == 0) {
                atomicAdd(&g_barrier, 1u);
                unsigned target = (unsigned)(t + 1) * (unsigned)gridDim.x;
                while (*(volatile unsigned*)&g_barrier < target) { }
            }
            __syncthreads();
            __threadfence();
        }
    }
}

// ---------------- embedding gather ----------------
__global__ void gather_emb(const int* __restrict__ x, const float* __restrict__ ew) {
    int m = blockIdx.x;            // t*B + b
    int b = m & 63;
    int t = m >> 6;
    int row = x[b * Tv + t];
    const float4* src = (const float4*)&ew[(long long)row * Ev];
    float4* dst = (float4*)&g_embT[(size_t)m * Ev];
    for (int i = threadIdx.x; i < Ev / 4; i += blockDim.x) dst[i] = src[i];
}

__global__ void zero_state() {
    int i = blockIdx.x * blockDim.x + threadIdx.x;
    if (i < Bv * Hv) { g_h[i] = 0.f; g_c[i] = 0.f; }
    if (i == 0) g_barrier = 0u;
}

// ---------------- attention scores ----------------
__global__ void scores_k(const float* __restrict__ v) {
    int warp = (blockIdx.x * blockDim.x + threadIdx.x) >> 5;
    int lane = threadIdx.x & 31;
    if (warp >= Tv * Bv) return;
    int b = warp & 63;
    const float* m1 = g_m1 + (size_t)warp * Av;
    const float* m2 = g_m2 + b * Av;
    float s = 0.f;
    for (int a = lane; a < Av; a += 32) s += tanhf(m1[a] + m2[a]) * v[a];
#pragma unroll
    for (int o = 16; o; o >>= 1) s += __shfl_xor_sync(0xffffffffu, s, o);
    if (!lane) g_sc[warp] = s;
}

__global__ void softmax_k() {
    int b = blockIdx.x;
    int t = threadIdx.x;
    __shared__ float red[Tv];
    float val = g_sc[t * Bv + b];
    red[t] = val; __syncthreads();
    for (int o = 128; o; o >>= 1) { if (t < o) red[t] = fmaxf(red[t], red[t + o]); __syncthreads(); }
    float mx = red[0]; __syncthreads();
    float e = expf(val - mx);
    red[t] = e; __syncthreads();
    for (int o = 128; o; o >>= 1) { if (t < o) red[t] += red[t + o]; __syncthreads(); }
    g_sc[t * Bv + b] = e / red[0];
}

__global__ void context_k() {
    int b = blockIdx.x;
    __shared__ float at[Tv];
    for (int t = threadIdx.x; t < Tv; t += blockDim.x) at[t] = g_sc[t * Bv + b];
    __syncthreads();
    for (int h = threadIdx.x; h < Hv; h += blockDim.x) {
        float s = 0.f;
#pragma unroll 4
        for (int t = 0; t < Tv; t++)
            s += g_seq1[((size_t)(t * Bv + b)) * Hv + h] * at[t];
        g_cat[b * 2 * Hv + h] = s;
        g_cat[b * 2 * Hv + Hv + h] = g_h[b * Hv + h];
    }
}

__global__ void logit_k(const float* __restrict__ ow, const float* __restrict__ ob,
                        float* __restrict__ out) {
    int idx = blockIdx.x;           // b*2 + c
    int b = idx >> 1, c = idx & 1;
    int lane = threadIdx.x;
    float s = 0.f;
    for (int k = lane; k < Hv; k += 32) s += g_nvec[b * Hv + k] * ow[c * Hv + k];
#pragma unroll
    for (int o = 16; o; o >>= 1) s += __shfl_xor_sync(0xffffffffu, s, o);
    if (!lane) out[idx] = s + ob[c];
}

// ---------------- host orchestration (14 graph nodes) ----------------
extern "C" void kernel_launch(void* const* d_in, const int* in_sizes, int n_in,
                              void* d_out, int out_size) {
    const int*   x      = (const int*)d_in[0];
    const float* embed_w= (const float*)d_in[1];
    const float* w_ih0  = (const float*)d_in[2];
    const float* w_hh0  = (const float*)d_in[3];
    const float* b_ih0  = (const float*)d_in[4];
    const float* b_hh0  = (const float*)d_in[5];
    const float* w_ih1  = (const float*)d_in[6];
    const float* w_hh1  = (const float*)d_in[7];
    const float* b_ih1  = (const float*)d_in[8];
    const float* b_hh1  = (const float*)d_in[9];
    const float* m1_w   = (const float*)d_in[10];
    const float* m1_b   = (const float*)d_in[11];
    const float* m2_w   = (const float*)d_in[12];
    const float* m2_b   = (const float*)d_in[13];
    const float* vv     = (const float*)d_in[14];
    const float* n_w    = (const float*)d_in[15];
    const float* n_b    = (const float*)d_in[16];
    const float* out_w  = (const float*)d_in[17];
    const float* out_b  = (const float*)d_in[18];
    float* out = (float*)d_out;

    float *p_embT, *p_xp, *p_seq0, *p_seq1, *p_h, *p_m1, *p_m2, *p_cat, *p_nvec;
    cudaGetSymbolAddress((void**)&p_embT, g_embT);
    cudaGetSymbolAddress((void**)&p_xp,   g_xp);
    cudaGetSymbolAddress((void**)&p_seq0, g_seq0);
    cudaGetSymbolAddress((void**)&p_seq1, g_seq1);
    cudaGetSymbolAddress((void**)&p_h,    g_h);
    cudaGetSymbolAddress((void**)&p_m1,   g_m1);
    cudaGetSymbolAddress((void**)&p_m2,   g_m2);
    cudaGetSymbolAddress((void**)&p_cat,  g_cat);
    cudaGetSymbolAddress((void**)&p_nvec, g_nvec);

    // embedding + x_proj layer 0 (biases folded)
    gather_emb<<<Tv * Bv, 128>>>(x, embed_w);
    sgemm<<<dim3(Gv / 64, (Tv * Bv) / 64), 128>>>(p_embT, Ev, w_ih0, Ev, p_xp, Gv,
                                                  Ev, b_ih0, b_hh0, 0);
    // layer 0 scan (single persistent kernel)
    zero_state<<<256, 256>>>();
    lstm_scan<<<SCAN_BLOCKS, 128>>>(w_hh0, p_xp, p_seq0);

    // x_proj layer 1
    sgemm<<<dim3(Gv / 64, (Tv * Bv) / 64), 128>>>(p_seq0, Hv, w_ih1, Hv, p_xp, Gv,
                                                  Hv, b_ih1, b_hh1, 0);
    // layer 1 scan
    zero_state<<<256, 256>>>();
    lstm_scan<<<SCAN_BLOCKS, 128>>>(w_hh1, p_xp, p_seq1);

    // attention
    sgemm<<<dim3(Av / 64, (Tv * Bv) / 64), 128>>>(p_seq1, Hv, m1_w, Hv, p_m1, Av,
                                                  Hv, m1_b, nullptr, 0);
    sgemm<<<dim3(Av / 64, 1), 128>>>(p_h, Hv, m2_w, Hv, p_m2, Av,
                                     Hv, m2_b, nullptr, 0);
    scores_k<<<(Tv * Bv * 32) / 256, 256>>>(vv);
    softmax_k<<<Bv, Tv>>>();
    context_k<<<Bv, 256>>>();
    sgemm<<<dim3(Hv / 64, 1), 128>>>(p_cat, 2 * Hv, n_w, 2 * Hv, p_nvec, Hv,
                                     2 * Hv, n_b, nullptr, 1);
    logit_k<<<Bv * Cv, 32>>>(out_w, out_b, out);
}

// round 5
// speedup vs baseline: 1.1568x; 1.1568x over previous
#include <cuda_runtime.h>
#include <cuda_bf16.h>
#include <cstdint>
#include <math.h>

#define Bv 64
#define Tv 256
#define Hv 1024
#define Ev 512
#define Av 512
#define Gv 4096   /* 4*H */
#define Cv 2
#define SCAN_BLOCKS 128
#define BH (Bv * Hv)

// ---------------- scratch (static device globals; no allocations) ----------------
__device__ __nv_bfloat16 g_A2[(size_t)Tv * Bv * 3 * Hv];   // packed split-bf16 A [16384][3072]
__device__ __nv_bfloat16 g_B2[(size_t)Gv * 3 * Hv];        // packed split-bf16 B [4096][3072]
__device__ float g_xp  [(size_t)Tv * Bv * Gv];             // [t*B+b][4H]
__device__ float g_seq1[(size_t)Tv * Bv * Hv];
__device__ float g_h   [2 * BH];                           // double-buffered per step
__device__ float g_c   [BH];
__device__ float g_m1  [(size_t)Tv * Bv * Av];
__device__ float g_m2  [Bv * Av];
__device__ float g_sc  [Tv * Bv];
__device__ float g_cat [Bv * 2 * Hv];
__device__ float g_nvec[Bv * Hv];
__device__ unsigned g_barrier;

// ---------------- helpers ----------------
__device__ __forceinline__ uint32_t smem_u32(const void* p) {
    uint32_t a;
    asm("{ .reg .u64 t; cvta.to.shared.u64 t, %1; cvt.u32.u64 %0, t; }" : "=r"(a) : "l"(p));
    return a;
}
__device__ __forceinline__ void cp16(uint32_t s, const void* g) {
    asm volatile("cp.async.cg.shared.global [%0], [%1], 16;" :: "r"(s), "l"(g));
}
#define CP_COMMIT() asm volatile("cp.async.commit_group;" ::: "memory")
#define CP_WAIT(n)  asm volatile("cp.async.wait_group %0;" :: "n"(n) : "memory")

__device__ __forceinline__ void ldm_x4(uint32_t* r, uint32_t addr) {
    asm volatile("ldmatrix.sync.aligned.m8n8.x4.shared.b16 {%0,%1,%2,%3}, [%4];"
        : "=r"(r[0]), "=r"(r[1]), "=r"(r[2]), "=r"(r[3]) : "r"(addr));
}
__device__ __forceinline__ void mma16816(float* c, const uint32_t* a, uint32_t b0, uint32_t b1) {
    asm volatile("mma.sync.aligned.m16n8k16.row.col.f32.bf16.bf16.f32 "
        "{%0,%1,%2,%3}, {%4,%5,%6,%7}, {%8,%9}, {%0,%1,%2,%3};"
        : "+f"(c[0]), "+f"(c[1]), "+f"(c[2]), "+f"(c[3])
        : "r"(a[0]), "r"(a[1]), "r"(a[2]), "r"(a[3]), "r"(b0), "r"(b1));
}

union f2u { float2 f; unsigned long long u; };
__device__ __forceinline__ float2 ffma2(float2 a, float2 b, float2 c) {
    f2u A, B, C, D; A.f = a; B.f = b; C.f = c;
    asm("fma.rn.f32x2 %0, %1, %2, %3;" : "=l"(D.u) : "l"(A.u), "l"(B.u), "l"(C.u));
    return D.f;
}
__device__ __forceinline__ float sigmoidf_(float x) { return 1.f / (1.f + expf(-x)); }

// ================= mma.sync split-bf16 GEMM =================
// C[m][n] = A2[m][:K3] . B2[n][:K3]  (bf16 x bf16 -> fp32)
// BM=BN=128, BK=32, 256 threads (8 warps, 4m x 2n), warp tile 32x64.
// Smem tiles: 128 rows x 32 bf16 (64B rows) with XOR swizzle kq^=(r>>1)&3 -> conflict-free ldmatrix.
__device__ __forceinline__ uint32_t sw_off(int r, int kq) {
    return (uint32_t)(r * 64 + ((kq ^ ((r >> 1) & 3)) << 4));
}

__global__ __launch_bounds__(256) void mma_gemm(
    const __nv_bfloat16* __restrict__ A2, const __nv_bfloat16* __restrict__ B2,
    float* __restrict__ C, int ldc, int K3,
    const float* __restrict__ bias1, const float* __restrict__ bias2)
{
    __shared__ __align__(128) __nv_bfloat16 AsBuf[2][128 * 32];
    __shared__ __align__(128) __nv_bfloat16 BsBuf[2][128 * 32];

    const int tid = threadIdx.x, wid = tid >> 5, lid = tid & 31;
    const int wm = wid >> 1, wn = wid & 1;
    const long long mBase = (long long)blockIdx.y * 128;
    const int nBase = blockIdx.x * 128;
    const uint32_t uA = smem_u32(AsBuf), uB = smem_u32(BsBuf);

    const __nv_bfloat16* Ag = A2 + mBase * (size_t)K3;
    const __nv_bfloat16* Bg = B2 + (size_t)nBase * K3;

    float acc[2][8][4];
#pragma unroll
    for (int i = 0; i < 2; i++)
#pragma unroll
        for (int j = 0; j < 8; j++)
#pragma unroll
            for (int q = 0; q < 4; q++) acc[i][j][q] = 0.f;

    const int NS = K3 / 32;
    // per-thread load mapping: 2 chunks of 16B per tile
    const int c0r = (tid * 2) >> 2,     c0q = (tid * 2) & 3;
    const int c1r = (tid * 2 + 1) >> 2, c1q = (tid * 2 + 1) & 3;

    // ldmatrix lane pieces
    const int aR = ((lid >> 3) & 1) * 8 + (lid & 7);   // + wm*32 + fm*16
    const int aQ = (lid >> 4) & 1;                      // + kk/8
    const int bR = ((lid >> 4) & 1) * 8 + (lid & 7);   // + wn*64 + jp*16
    const int bQ = (lid >> 3) & 1;

    // preload stage 0
    {
        uint32_t d = uA;
        cp16(d + sw_off(c0r, c0q), Ag + (size_t)c0r * K3 + c0q * 8);
        cp16(d + sw_off(c1r, c1q), Ag + (size_t)c1r * K3 + c1q * 8);
        d = uB;
        cp16(d + sw_off(c0r, c0q), Bg + (size_t)c0r * K3 + c0q * 8);
        cp16(d + sw_off(c1r, c1q), Bg + (size_t)c1r * K3 + c1q * 8);
        CP_COMMIT();
    }

    for (int s = 0; s < NS; s++) {
        if (s + 1 < NS) {
            const int nb = (s + 1) & 1;
            const int k0 = (s + 1) * 32;
            uint32_t d = uA + nb * 8192;
            cp16(d + sw_off(c0r, c0q), Ag + (size_t)c0r * K3 + k0 + c0q * 8);
            cp16(d + sw_off(c1r, c1q), Ag + (size_t)c1r * K3 + k0 + c1q * 8);
            d = uB + nb * 8192;
            cp16(d + sw_off(c0r, c0q), Bg + (size_t)c0r * K3 + k0 + c0q * 8);
            cp16(d + sw_off(c1r, c1q), Bg + (size_t)c1r * K3 + k0 + c1q * 8);
            CP_COMMIT();
            CP_WAIT(1);
        } else {
            CP_WAIT(0);
        }
        __syncthreads();

        const uint32_t bufA = uA + (s & 1) * 8192;
        const uint32_t bufB = uB + (s & 1) * 8192;
#pragma unroll
        for (int kk8 = 0; kk8 < 4; kk8 += 2) {    // kk = kk8*8 (0, 16)
            uint32_t a[2][4];
#pragma unroll
            for (int fm = 0; fm < 2; fm++) {
                int r = wm * 32 + fm * 16 + aR;
                ldm_x4(a[fm], bufA + sw_off(r, kk8 + aQ));
            }
#pragma unroll
            for (int jp = 0; jp < 4; jp++) {
                uint32_t b[4];
                int r = wn * 64 + jp * 16 + bR;
                ldm_x4(b, bufB + sw_off(r, kk8 + bQ));
#pragma unroll
                for (int fm = 0; fm < 2; fm++) {
                    mma16816(acc[fm][2 * jp],     a[fm], b[0], b[1]);
                    mma16816(acc[fm][2 * jp + 1], a[fm], b[2], b[3]);
                }
            }
        }
        __syncthreads();
    }

    // epilogue
    const int gid = lid >> 2, tig = lid & 3;
#pragma unroll
    for (int fm = 0; fm < 2; fm++) {
#pragma unroll
        for (int j = 0; j < 8; j++) {
            int n = nBase + wn * 64 + j * 8 + tig * 2;
            float b0 = 0.f, b1 = 0.f;
            if (bias1) { b0 = bias1[n]; b1 = bias1[n + 1]; }
            if (bias2) { b0 += bias2[n]; b1 += bias2[n + 1]; }
            long long m0 = mBase + wm * 32 + fm * 16 + gid;
            float* r0 = C + m0 * (long long)ldc + n;
            r0[0] = acc[fm][j][0] + b0;
            r0[1] = acc[fm][j][1] + b1;
            float* r1 = r0 + 8LL * ldc;
            r1[0] = acc[fm][j][2] + b0;
            r1[1] = acc[fm][j][3] + b1;
        }
    }
}

// ---------------- packing kernels ----------------
// B2[n][3K] = [hi | lo | hi]   (pairs with A2 = [hi | hi | lo])
__global__ void pack_B(const float* __restrict__ W, int N, int K) {
    int i = blockIdx.x * blockDim.x + threadIdx.x;
    if (i >= N * K) return;
    int n = i / K, k = i - n * K;
    float a = W[i];
    __nv_bfloat16 hi = __float2bfloat16(a);
    __nv_bfloat16 lo = __float2bfloat16(a - __bfloat162float(hi));
    size_t base = (size_t)n * (3 * K) + k;
    g_B2[base] = hi; g_B2[base + K] = lo; g_B2[base + 2 * K] = hi;
}

// embedding gather into packed A2: [0:K]=hi, [K:2K]=hi, [2K:3K]=lo
__global__ void gather_pack(const int* __restrict__ x, const float* __restrict__ ew) {
    int m = blockIdx.x;            // t*B + b
    int b = m & 63, t = m >> 6;
    int row = x[b * Tv + t];
    const float* src = ew + (size_t)row * Ev;
    __nv_bfloat16* dst = g_A2 + (size_t)m * (3 * Ev);
    for (int k = threadIdx.x; k < Ev; k += blockDim.x) {
        float a = src[k];
        __nv_bfloat16 hi = __float2bfloat16(a);
        __nv_bfloat16 lo = __float2bfloat16(a - __bfloat162float(hi));
        dst[k] = hi; dst[Ev + k] = hi; dst[2 * Ev + k] = lo;
    }
}

__global__ void zero_state() {
    int i = blockIdx.x * blockDim.x + threadIdx.x;
    if (i < BH) { g_h[i] = 0.f; g_c[i] = 0.f; }
    if (i == 0) g_barrier = 0u;
}

// ---------------- persistent LSTM scan (256 threads, double-buffered h) ----------------
__global__ __launch_bounds__(256) void lstm_scan(
    const float* __restrict__ W,    // w_hh [4096][1024]
    const float* __restrict__ xp,   // [T*B][4096], biases folded
    float* __restrict__ seq,        // may be null
    __nv_bfloat16* __restrict__ a2)
{
    __shared__ __align__(16) float As[16][72];   // h chunk [k][b]
    __shared__ __align__(16) float Bs[16][36];   // W chunk [k][o]
    __shared__ __align__(16) float Cs[64][36];   // gates

    const int tid = threadIdx.x;
    const int u0 = blockIdx.x * 8;
    const int tx = tid & 15;        // out pair o = 2tx, 2tx+1
    const int ty = tid >> 4;        // 0..15, batch group of 4

    const int bA = tid >> 2, kqA = tid & 3;
    const int oB = tid >> 2, kqB = tid & 3;
    const long long wrowB = (long long)((oB >> 3) * Hv + u0 + (oB & 7)) * Hv;
    const int o2 = 2 * tx;
    const int growx = (o2 >> 3) * Hv + u0 + (o2 & 7);

    for (int t = 0; t < Tv; t++) {
        const float* hr = g_h + (t & 1) * BH;
        float* hw = g_h + ((t + 1) & 1) * BH;

        float2 acc[4];
#pragma unroll
        for (int i = 0; i < 4; i++) acc[i] = make_float2(0.f, 0.f);

        for (int k0 = 0; k0 < Hv; k0 += 16) {
            {
                float4 va = __ldcg((const float4*)&hr[bA * Hv + k0 + kqA * 4]);
                As[kqA * 4 + 0][bA] = va.x; As[kqA * 4 + 1][bA] = va.y;
                As[kqA * 4 + 2][bA] = va.z; As[kqA * 4 + 3][bA] = va.w;
            }
            if (tid < 128) {
                float4 vb = *(const float4*)&W[wrowB + k0 + kqB * 4];
                Bs[kqB * 4 + 0][oB] = vb.x; Bs[kqB * 4 + 1][oB] = vb.y;
                Bs[kqB * 4 + 2][oB] = vb.z; Bs[kqB * 4 + 3][oB] = vb.w;
            }
            __syncthreads();
#pragma unroll
            for (int kk = 0; kk < 16; kk++) {
                float4 a = *(const float4*)&As[kk][ty * 4];
                float2 bp = *(const float2*)&Bs[kk][tx * 2];
                acc[0] = ffma2(make_float2(a.x, a.x), bp, acc[0]);
                acc[1] = ffma2(make_float2(a.y, a.y), bp, acc[1]);
                acc[2] = ffma2(make_float2(a.z, a.z), bp, acc[2]);
                acc[3] = ffma2(make_float2(a.w, a.w), bp, acc[3]);
            }
            __syncthreads();
        }

#pragma unroll
        for (int i = 0; i < 4; i++) {
            int b = ty * 4 + i;
            float2 xv = *(const float2*)&xp[((size_t)(t * Bv + b)) * Gv + growx];
            Cs[b][o2]     = acc[i].x + xv.x;
            Cs[b][o2 + 1] = acc[i].y + xv.y;
        }
        __syncthreads();

#pragma unroll
        for (int q = 0; q < 2; q++) {
            int p = tid + q * 256;
            int b = p >> 3, j = p & 7;
            float gi = Cs[b][j];
            float gf = Cs[b][8 + j];
            float gg = Cs[b][16 + j];
            float go = Cs[b][24 + j];
            int idx = b * Hv + u0 + j;
            float c = sigmoidf_(gf) * g_c[idx] + sigmoidf_(gi) * tanhf(gg);
            float h = sigmoidf_(go) * tanhf(c);
            g_c[idx] = c;
            hw[idx] = h;
            if (seq) seq[((size_t)(t * Bv + b)) * Hv + u0 + j] = h;
            __nv_bfloat16 hh = __float2bfloat16(h);
            __nv_bfloat16 hl = __float2bfloat16(h - __bfloat162float(hh));
            size_t abase = ((size_t)(t * Bv + b)) * (3 * Hv) + u0 + j;
            a2[abase] = hh; a2[abase + Hv] = hh; a2[abase + 2 * Hv] = hl;
        }

        if (t < Tv - 1) {
            __threadfence();
            __syncthreads();
            if (tid == 0) {
                atomicAdd(&g_barrier, 1u);
                unsigned target = (unsigned)(t + 1) * (unsigned)gridDim.x;
                while (*(volatile unsigned*)&g_barrier < target) { }
            }
            __syncthreads();
            __threadfence();
        }
    }
}

// ---------------- small FFMA2 sgemm (tiny GEMMs: m2, n_vec) ----------------
#define BKt 16
__global__ __launch_bounds__(128) void sgemm(
    const float* __restrict__ A, int lda,
    const float* __restrict__ B, int ldb,
    float* __restrict__ C, int ldc,
    int K, const float* __restrict__ bias1, int act)
{
    __shared__ __align__(16) float As[BKt][64 + 4];
    __shared__ __align__(16) float Bs[BKt][64 + 4];
    const int tid = threadIdx.x;
    const int nBase = blockIdx.x * 64;
    const long long mBase = (long long)blockIdx.y * 64;
    const int ty = tid >> 4, tx = tid & 15;

    float2 acc[8][2];
#pragma unroll
    for (int i = 0; i < 8; i++) { acc[i][0] = make_float2(0.f, 0.f); acc[i][1] = make_float2(0.f, 0.f); }

    for (int k0 = 0; k0 < K; k0 += BKt) {
#pragma unroll
        for (int i = 0; i < 2; i++) {
            int f = i * 128 + tid;
            int m = f >> 2, kq = f & 3;
            float4 va = *(const float4*)&A[(mBase + m) * (long long)lda + k0 + kq * 4];
            As[kq * 4 + 0][m] = va.x; As[kq * 4 + 1][m] = va.y;
            As[kq * 4 + 2][m] = va.z; As[kq * 4 + 3][m] = va.w;
            float4 vb = *(const float4*)&B[(long long)(nBase + m) * ldb + k0 + kq * 4];
            Bs[kq * 4 + 0][m] = vb.x; Bs[kq * 4 + 1][m] = vb.y;
            Bs[kq * 4 + 2][m] = vb.z; Bs[kq * 4 + 3][m] = vb.w;
        }
        __syncthreads();
#pragma unroll
        for (int kk = 0; kk < BKt; kk++) {
            float4 a0 = *(const float4*)&As[kk][ty * 8];
            float4 a1 = *(const float4*)&As[kk][ty * 8 + 4];
            float4 b4 = *(const float4*)&Bs[kk][tx * 4];
            float2 b01 = make_float2(b4.x, b4.y);
            float2 b23 = make_float2(b4.z, b4.w);
            float av[8] = {a0.x, a0.y, a0.z, a0.w, a1.x, a1.y, a1.z, a1.w};
#pragma unroll
            for (int i = 0; i < 8; i++) {
                float2 ad = make_float2(av[i], av[i]);
                acc[i][0] = ffma2(ad, b01, acc[i][0]);
                acc[i][1] = ffma2(ad, b23, acc[i][1]);
            }
        }
        __syncthreads();
    }

    float4 bb = make_float4(0.f, 0.f, 0.f, 0.f);
    if (bias1) bb = *(const float4*)&bias1[nBase + tx * 4];
#pragma unroll
    for (int i = 0; i < 8; i++) {
        long long m = mBase + ty * 8 + i;
        float4 r = make_float4(acc[i][0].x + bb.x, acc[i][0].y + bb.y,
                               acc[i][1].x + bb.z, acc[i][1].y + bb.w);
        if (act == 1) { r.x = tanhf(r.x); r.y = tanhf(r.y); r.z = tanhf(r.z); r.w = tanhf(r.w); }
        *(float4*)&C[m * (long long)ldc + nBase + tx * 4] = r;
    }
}

// ---------------- attention tail ----------------
__global__ void scores_k(const float* __restrict__ v) {
    int warp = (blockIdx.x * blockDim.x + threadIdx.x) >> 5;
    int lane = threadIdx.x & 31;
    if (warp >= Tv * Bv) return;
    int b = warp & 63;
    const float* m1 = g_m1 + (size_t)warp * Av;
    const float* m2 = g_m2 + b * Av;
    float s = 0.f;
    for (int a = lane; a < Av; a += 32) s += tanhf(m1[a] + m2[a]) * v[a];
#pragma unroll
    for (int o = 16; o; o >>= 1) s += __shfl_xor_sync(0xffffffffu, s, o);
    if (!lane) g_sc[warp] = s;
}

__global__ void softmax_k() {
    int b = blockIdx.x;
    int t = threadIdx.x;
    __shared__ float red[Tv];
    float val = g_sc[t * Bv + b];
    red[t] = val; __syncthreads();
    for (int o = 128; o; o >>= 1) { if (t < o) red[t] = fmaxf(red[t], red[t + o]); __syncthreads(); }
    float mx = red[0]; __syncthreads();
    float e = expf(val - mx);
    red[t] = e; __syncthreads();
    for (int o = 128; o; o >>= 1) { if (t < o) red[t] += red[t + o]; __syncthreads(); }
    g_sc[t * Bv + b] = e / red[0];
}

__global__ void context_k() {
    int b = blockIdx.x;
    __shared__ float at[Tv];
    for (int t = threadIdx.x; t < Tv; t += blockDim.x) at[t] = g_sc[t * Bv + b];
    __syncthreads();
    for (int h = threadIdx.x; h < Hv; h += blockDim.x) {
        float s = 0.f;
#pragma unroll 4
        for (int t = 0; t < Tv; t++)
            s += g_seq1[((size_t)(t * Bv + b)) * Hv + h] * at[t];
        g_cat[b * 2 * Hv + h] = s;
        g_cat[b * 2 * Hv + Hv + h] = g_h[b * Hv + h];   // final h in buffer 0
    }
}

__global__ void logit_k(const float* __restrict__ ow, const float* __restrict__ ob,
                        float* __restrict__ out) {
    int idx = blockIdx.x;
    int b = idx >> 1, c = idx & 1;
    int lane = threadIdx.x;
    float s = 0.f;
    for (int k = lane; k < Hv; k += 32) s += g_nvec[b * Hv + k] * ow[c * Hv + k];
#pragma unroll
    for (int o = 16; o; o >>= 1) s += __shfl_xor_sync(0xffffffffu, s, o);
    if (!lane) out[idx] = s + ob[c];
}

// ---------------- host orchestration ----------------
extern "C" void kernel_launch(void* const* d_in, const int* in_sizes, int n_in,
                              void* d_out, int out_size) {
    const int*   x      = (const int*)d_in[0];
    const float* embed_w= (const float*)d_in[1];
    const float* w_ih0  = (const float*)d_in[2];
    const float* w_hh0  = (const float*)d_in[3];
    const float* b_ih0  = (const float*)d_in[4];
    const float* b_hh0  = (const float*)d_in[5];
    const float* w_ih1  = (const float*)d_in[6];
    const float* w_hh1  = (const float*)d_in[7];
    const float* b_ih1  = (const float*)d_in[8];
    const float* b_hh1  = (const float*)d_in[9];
    const float* m1_w   = (const float*)d_in[10];
    const float* m1_b   = (const float*)d_in[11];
    const float* m2_w   = (const float*)d_in[12];
    const float* m2_b   = (const float*)d_in[13];
    const float* vv     = (const float*)d_in[14];
    const float* n_w    = (const float*)d_in[15];
    const float* n_b    = (const float*)d_in[16];
    const float* out_w  = (const float*)d_in[17];
    const float* out_b  = (const float*)d_in[18];
    float* out = (float*)d_out;

    __nv_bfloat16 *p_A2, *p_B2;
    float *p_xp, *p_seq1, *p_h, *p_m1, *p_m2, *p_cat, *p_nvec;
    cudaGetSymbolAddress((void**)&p_A2,   g_A2);
    cudaGetSymbolAddress((void**)&p_B2,   g_B2);
    cudaGetSymbolAddress((void**)&p_xp,   g_xp);
    cudaGetSymbolAddress((void**)&p_seq1, g_seq1);
    cudaGetSymbolAddress((void**)&p_h,    g_h);
    cudaGetSymbolAddress((void**)&p_m1,   g_m1);
    cudaGetSymbolAddress((void**)&p_m2,   g_m2);
    cudaGetSymbolAddress((void**)&p_cat,  g_cat);
    cudaGetSymbolAddress((void**)&p_nvec, g_nvec);

    // ---- layer 0 ----
    gather_pack<<<Tv * Bv, 128>>>(x, embed_w);
    pack_B<<<(Gv * Ev + 255) / 256, 256>>>(w_ih0, Gv, Ev);
    mma_gemm<<<dim3(Gv / 128, (Tv * Bv) / 128), 256>>>(p_A2, p_B2, p_xp, Gv,
                                                       3 * Ev, b_ih0, b_hh0);
    zero_state<<<256, 256>>>();
    lstm_scan<<<SCAN_BLOCKS, 256>>>(w_hh0, p_xp, nullptr, p_A2);

    // ---- layer 1 ----
    pack_B<<<(Gv * Hv + 255) / 256, 256>>>(w_ih1, Gv, Hv);
    mma_gemm<<<dim3(Gv / 128, (Tv * Bv) / 128), 256>>>(p_A2, p_B2, p_xp, Gv,
                                                       3 * Hv, b_ih1, b_hh1);
    zero_state<<<256, 256>>>();
    lstm_scan<<<SCAN_BLOCKS, 256>>>(w_hh1, p_xp, p_seq1, p_A2);

    // ---- attention ----
    pack_B<<<(Av * Hv + 255) / 256, 256>>>(m1_w, Av, Hv);
    mma_gemm<<<dim3(Av / 128, (Tv * Bv) / 128), 256>>>(p_A2, p_B2, p_m1, Av,
                                                       3 * Hv, m1_b, nullptr);
    sgemm<<<dim3(Av / 64, 1), 128>>>(p_h, Hv, m2_w, Hv, p_m2, Av, Hv, m2_b, 0);
    scores_k<<<(Tv * Bv * 32) / 256, 256>>>(vv);
    softmax_k<<<Bv, Tv>>>();
    context_k<<<Bv, 256>>>();
    sgemm<<<dim3(Hv / 64, 1), 128>>>(p_cat, 2 * Hv, n_w, 2 * Hv, p_nvec, Hv, 2 * Hv, n_b, 1);
    logit_k<<<Bv * Cv, 32>>>(out_w, out_b, out);
}

// round 6
// speedup vs baseline: 2.4160x; 2.0885x over previous
#include <cuda_runtime.h>
#include <cuda_bf16.h>
#include <cstdint>
#include <math.h>

#define Bv 64
#define Tv 256
#define Hv 1024
#define Ev 512
#define Av 512
#define Gv 4096   /* 4*H */
#define Cv 2
#define SCAN_BLOCKS 128
#define BH (Bv * Hv)

#define WSLICE 196608              /* 32 rows * 3072 bf16 * 2B */
#define ABUF 8192                  /* 64 rows * 64 bf16 * 2B   */
#define SCAN_SMEM (WSLICE + 4 * ABUF)

// ---------------- scratch (static device globals; no allocations) ----------------
__device__ __nv_bfloat16 g_A2[(size_t)Tv * Bv * 3 * Hv];   // packed split-bf16 A for big GEMMs
__device__ __nv_bfloat16 g_B2[(size_t)Gv * 3 * Hv];        // packed split-bf16 B for big GEMMs
__device__ __nv_bfloat16 g_WS[(size_t)Gv * 3 * Hv];        // per-block swizzled W_hh slices
__device__ __nv_bfloat16 g_HS[2 * 64 * 3072];              // split h, double-buffered
__device__ float g_xp  [(size_t)Tv * Bv * Gv];
__device__ float g_seq1[(size_t)Tv * Bv * Hv];
__device__ float g_h   [BH];
__device__ float g_c   [BH];
__device__ float g_m1  [(size_t)Tv * Bv * Av];
__device__ float g_m2  [Bv * Av];
__device__ float g_sc  [Tv * Bv];
__device__ float g_cat [Bv * 2 * Hv];
__device__ float g_nvec[Bv * Hv];
__device__ unsigned g_barrier;

// ---------------- helpers ----------------
__device__ __forceinline__ uint32_t smem_u32(const void* p) {
    uint32_t a;
    asm("{ .reg .u64 t; cvta.to.shared.u64 t, %1; cvt.u32.u64 %0, t; }" : "=r"(a) : "l"(p));
    return a;
}
__device__ __forceinline__ void cp16(uint32_t s, const void* g) {
    asm volatile("cp.async.cg.shared.global [%0], [%1], 16;" :: "r"(s), "l"(g));
}
#define CP_COMMIT() asm volatile("cp.async.commit_group;" ::: "memory")
#define CP_WAIT(n)  asm volatile("cp.async.wait_group %0;" :: "n"(n) : "memory")

__device__ __forceinline__ void ldm_x4(uint32_t* r, uint32_t addr) {
    asm volatile("ldmatrix.sync.aligned.m8n8.x4.shared.b16 {%0,%1,%2,%3}, [%4];"
        : "=r"(r[0]), "=r"(r[1]), "=r"(r[2]), "=r"(r[3]) : "r"(addr));
}
__device__ __forceinline__ void mma16816(float* c, const uint32_t* a, uint32_t b0, uint32_t b1) {
    asm volatile("mma.sync.aligned.m16n8k16.row.col.f32.bf16.bf16.f32 "
        "{%0,%1,%2,%3}, {%4,%5,%6,%7}, {%8,%9}, {%0,%1,%2,%3};"
        : "+f"(c[0]), "+f"(c[1]), "+f"(c[2]), "+f"(c[3])
        : "r"(a[0]), "r"(a[1]), "r"(a[2]), "r"(a[3]), "r"(b0), "r"(b1));
}

union f2u { float2 f; unsigned long long u; };
__device__ __forceinline__ float2 ffma2(float2 a, float2 b, float2 c) {
    f2u A, B, C, D; A.f = a; B.f = b; C.f = c;
    asm("fma.rn.f32x2 %0, %1, %2, %3;" : "=l"(D.u) : "l"(A.u), "l"(B.u), "l"(C.u));
    return D.f;
}
__device__ __forceinline__ float sigmoidf_(float x) { return 1.f / (1.f + expf(-x)); }

// XOR swizzle for 64B-row tiles (validated in R5): conflict-free ldmatrix
__device__ __host__ __forceinline__ uint32_t sw_off(int r, int kq) {
    return (uint32_t)(r * 64 + ((kq ^ ((r >> 1) & 3)) << 4));
}

// ================= mma.sync split-bf16 GEMM (unchanged from R5, passing) =================
__global__ __launch_bounds__(256) void mma_gemm(
    const __nv_bfloat16* __restrict__ A2, const __nv_bfloat16* __restrict__ B2,
    float* __restrict__ C, int ldc, int K3,
    const float* __restrict__ bias1, const float* __restrict__ bias2)
{
    __shared__ __align__(128) __nv_bfloat16 AsBuf[2][128 * 32];
    __shared__ __align__(128) __nv_bfloat16 BsBuf[2][128 * 32];

    const int tid = threadIdx.x, wid = tid >> 5, lid = tid & 31;
    const int wm = wid >> 1, wn = wid & 1;
    const long long mBase = (long long)blockIdx.y * 128;
    const int nBase = blockIdx.x * 128;
    const uint32_t uA = smem_u32(AsBuf), uB = smem_u32(BsBuf);

    const __nv_bfloat16* Ag = A2 + mBase * (size_t)K3;
    const __nv_bfloat16* Bg = B2 + (size_t)nBase * K3;

    float acc[2][8][4];
#pragma unroll
    for (int i = 0; i < 2; i++)
#pragma unroll
        for (int j = 0; j < 8; j++)
#pragma unroll
            for (int q = 0; q < 4; q++) acc[i][j][q] = 0.f;

    const int NS = K3 / 32;
    const int c0r = (tid * 2) >> 2,     c0q = (tid * 2) & 3;
    const int c1r = (tid * 2 + 1) >> 2, c1q = (tid * 2 + 1) & 3;

    const int aR = ((lid >> 3) & 1) * 8 + (lid & 7);
    const int aQ = (lid >> 4) & 1;
    const int bR = ((lid >> 4) & 1) * 8 + (lid & 7);
    const int bQ = (lid >> 3) & 1;

    {
        uint32_t d = uA;
        cp16(d + sw_off(c0r, c0q), Ag + (size_t)c0r * K3 + c0q * 8);
        cp16(d + sw_off(c1r, c1q), Ag + (size_t)c1r * K3 + c1q * 8);
        d = uB;
        cp16(d + sw_off(c0r, c0q), Bg + (size_t)c0r * K3 + c0q * 8);
        cp16(d + sw_off(c1r, c1q), Bg + (size_t)c1r * K3 + c1q * 8);
        CP_COMMIT();
    }

    for (int s = 0; s < NS; s++) {
        if (s + 1 < NS) {
            const int nb = (s + 1) & 1;
            const int k0 = (s + 1) * 32;
            uint32_t d = uA + nb * 8192;
            cp16(d + sw_off(c0r, c0q), Ag + (size_t)c0r * K3 + k0 + c0q * 8);
            cp16(d + sw_off(c1r, c1q), Ag + (size_t)c1r * K3 + k0 + c1q * 8);
            d = uB + nb * 8192;
            cp16(d + sw_off(c0r, c0q), Bg + (size_t)c0r * K3 + k0 + c0q * 8);
            cp16(d + sw_off(c1r, c1q), Bg + (size_t)c1r * K3 + k0 + c1q * 8);
            CP_COMMIT();
            CP_WAIT(1);
        } else {
            CP_WAIT(0);
        }
        __syncthreads();

        const uint32_t bufA = uA + (s & 1) * 8192;
        const uint32_t bufB = uB + (s & 1) * 8192;
#pragma unroll
        for (int kk8 = 0; kk8 < 4; kk8 += 2) {
            uint32_t a[2][4];
#pragma unroll
            for (int fm = 0; fm < 2; fm++) {
                int r = wm * 32 + fm * 16 + aR;
                ldm_x4(a[fm], bufA + sw_off(r, kk8 + aQ));
            }
#pragma unroll
            for (int jp = 0; jp < 4; jp++) {
                uint32_t b[4];
                int r = wn * 64 + jp * 16 + bR;
                ldm_x4(b, bufB + sw_off(r, kk8 + bQ));
#pragma unroll
                for (int fm = 0; fm < 2; fm++) {
                    mma16816(acc[fm][2 * jp],     a[fm], b[0], b[1]);
                    mma16816(acc[fm][2 * jp + 1], a[fm], b[2], b[3]);
                }
            }
        }
        __syncthreads();
    }

    const int gid = lid >> 2, tig = lid & 3;
#pragma unroll
    for (int fm = 0; fm < 2; fm++) {
#pragma unroll
        for (int j = 0; j < 8; j++) {
            int n = nBase + wn * 64 + j * 8 + tig * 2;
            float b0 = 0.f, b1 = 0.f;
            if (bias1) { b0 = bias1[n]; b1 = bias1[n + 1]; }
            if (bias2) { b0 += bias2[n]; b1 += bias2[n + 1]; }
            long long m0 = mBase + wm * 32 + fm * 16 + gid;
            float* r0 = C + m0 * (long long)ldc + n;
            r0[0] = acc[fm][j][0] + b0;
            r0[1] = acc[fm][j][1] + b1;
            float* r1 = r0 + 8LL * ldc;
            r1[0] = acc[fm][j][2] + b0;
            r1[1] = acc[fm][j][3] + b1;
        }
    }
}

// ---------------- packing kernels ----------------
// big-GEMM B: [hi | lo | hi] (pairs with A = [hi | hi | lo])
__global__ void pack_B(const float* __restrict__ W, int N, int K) {
    int i = blockIdx.x * blockDim.x + threadIdx.x;
    if (i >= N * K) return;
    int n = i / K, k = i - n * K;
    float a = W[i];
    __nv_bfloat16 hi = __float2bfloat16(a);
    __nv_bfloat16 lo = __float2bfloat16(a - __bfloat162float(hi));
    size_t base = (size_t)n * (3 * K) + k;
    g_B2[base] = hi; g_B2[base + K] = lo; g_B2[base + 2 * K] = hi;
}

// scan weights: per-block pre-swizzled smem image.
// block bi owns W rows {g*1024 + bi*8 + j}; local row r = g*8+j; cols [Whi|Wlo|Whi].
__global__ void pack_WS(const float* __restrict__ W) {
    int i = blockIdx.x * blockDim.x + threadIdx.x;   // over Gv*Hv
    if (i >= Gv * Hv) return;
    int n = i >> 10, k = i & 1023;
    float a = W[i];
    __nv_bfloat16 hi = __float2bfloat16(a);
    __nv_bfloat16 lo = __float2bfloat16(a - __bfloat162float(hi));
    int g = n >> 10, bi = (n & 1023) >> 3, j = n & 7;
    int r = g * 8 + j;
    char* base = (char*)g_WS + (size_t)bi * WSLICE;
#pragma unroll
    for (int term = 0; term < 3; term++) {
        int kk = term * 1024 + k;
        __nv_bfloat16 v = (term == 1) ? lo : hi;
        *(__nv_bfloat16*)(base + (size_t)(kk >> 5) * 2048
                          + sw_off(r, (kk >> 3) & 3) + (kk & 7) * 2) = v;
    }
}

// embedding gather into packed A2: [0:K]=hi, [K:2K]=hi, [2K:3K]=lo
__global__ void gather_pack(const int* __restrict__ x, const float* __restrict__ ew) {
    int m = blockIdx.x;            // t*B + b
    int b = m & 63, t = m >> 6;
    int row = x[b * Tv + t];
    const float* src = ew + (size_t)row * Ev;
    __nv_bfloat16* dst = g_A2 + (size_t)m * (3 * Ev);
    for (int k = threadIdx.x; k < Ev; k += blockDim.x) {
        float a = src[k];
        __nv_bfloat16 hi = __float2bfloat16(a);
        __nv_bfloat16 lo = __float2bfloat16(a - __bfloat162float(hi));
        dst[k] = hi; dst[Ev + k] = hi; dst[2 * Ev + k] = lo;
    }
}

__global__ void zero_state() {
    int i = blockIdx.x * blockDim.x + threadIdx.x;
    if (i < BH) { g_h[i] = 0.f; g_c[i] = 0.f; }
    if (i == 0) g_barrier = 0u;
}

// ---------------- persistent LSTM scan on tensor cores ----------------
// 128 blocks x 256 threads (8 warps: 4m x 2n). Block bi owns units u0=bi*8 -> 32 W rows.
// W slice resident in smem (192KB, loaded once). Per step: Y[64x32] = Hsplit[64x3072] . Wslice^T
// via mma.sync with a 4-buffer cp.async pipeline; fused pointwise; one grid barrier.
__global__ __launch_bounds__(256) void lstm_scan_mma(
    const __nv_bfloat16* __restrict__ WS,
    const float* __restrict__ xp,
    float* __restrict__ seq,            // nullable (layer1)
    __nv_bfloat16* __restrict__ a2)     // nullable (layer0 packed out)
{
    extern __shared__ __align__(128) char sm[];
    const int tid = threadIdx.x, wid = tid >> 5, lid = tid & 31;
    const int wm = wid >> 1, wn = wid & 1;
    const int bi = blockIdx.x, u0 = bi * 8;
    const uint32_t sW = smem_u32(sm);
    const uint32_t sA = sW + WSLICE;
    float* Cs = (float*)(sm + WSLICE);   // overlays A buffers (safe: disjoint in time)

    const int aR = ((lid >> 3) & 1) * 8 + (lid & 7);
    const int aQ = (lid >> 4) & 1;
    const int bR = ((lid >> 4) & 1) * 8 + (lid & 7);
    const int bQ = (lid >> 3) & 1;
    const int gid = lid >> 2, tig = lid & 3;

    // load W slice (192KB) into smem once
    {
        const char* wg = (const char*)WS + (size_t)bi * WSLICE;
        for (int i = tid; i < WSLICE / 16; i += 256)
            cp16(sW + (uint32_t)(i * 16), wg + (size_t)i * 16);
        CP_COMMIT(); CP_WAIT(0);
        __syncthreads();
    }

    const int pb0 = tid >> 3, pj = tid & 7;   // pointwise pairs: (pb0, pj), (pb0+32, pj)

    for (int t = 0; t < Tv; t++) {
        // prefetch xp gate biases (hidden under the K loop)
        float xv[2][4];
#pragma unroll
        for (int q = 0; q < 2; q++) {
            int b = pb0 + q * 32;
            const float* xr = xp + ((size_t)(t * Bv + b)) * Gv + u0 + pj;
#pragma unroll
            for (int g = 0; g < 4; g++) xv[q][g] = __ldg(xr + g * Hv);
        }

        if (t > 0) {
            const __nv_bfloat16* HS = g_HS + (size_t)(t & 1) * (64 * 3072);
            float acc[2][4];
#pragma unroll
            for (int j = 0; j < 2; j++)
#pragma unroll
                for (int q = 0; q < 4; q++) acc[j][q] = 0.f;

            // prefetch stages 0..2 (BK=64 each)
#pragma unroll
            for (int s = 0; s < 3; s++) {
                int k0 = s * 64;
#pragma unroll
                for (int q = 0; q < 2; q++) {
                    int id = tid * 2 + q;
                    int r = id >> 3, c16 = id & 7;
                    cp16(sA + s * ABUF + (c16 >> 2) * 4096 + sw_off(r, c16 & 3),
                         HS + (size_t)r * 3072 + k0 + c16 * 8);
                }
                CP_COMMIT();
            }

#pragma unroll 1
            for (int s = 0; s < 48; s++) {
                CP_WAIT(2);              // stage s resident
                __syncthreads();
                const uint32_t bufA = sA + (s & 3) * ABUF;
                const uint32_t bufW = sW + (uint32_t)s * 4096;
#pragma unroll
                for (int sub = 0; sub < 2; sub++) {
#pragma unroll
                    for (int kk8 = 0; kk8 < 4; kk8 += 2) {
                        uint32_t a[4], b[4];
                        ldm_x4(a, bufA + sub * 4096 + sw_off(wm * 16 + aR, kk8 + aQ));
                        ldm_x4(b, bufW + sub * 2048 + sw_off(wn * 16 + bR, kk8 + bQ));
                        mma16816(acc[0], a, b[0], b[1]);
                        mma16816(acc[1], a, b[2], b[3]);
                    }
                }
                if (s + 3 < 48) {        // refill buf (s+3)&3 == (s-1)&3, safe past this iter's sync
                    int k0 = (s + 3) * 64;
                    uint32_t d = sA + ((s + 3) & 3) * ABUF;
#pragma unroll
                    for (int q = 0; q < 2; q++) {
                        int id = tid * 2 + q;
                        int r = id >> 3, c16 = id & 7;
                        cp16(d + (c16 >> 2) * 4096 + sw_off(r, c16 & 3),
                             HS + (size_t)r * 3072 + k0 + c16 * 8);
                    }
                }
                CP_COMMIT();             // always commit (keeps group accounting exact)
            }
            __syncthreads();             // A buffers idle -> Cs overlay

            // exchange gate partials through Cs [64][33]
#pragma unroll
            for (int j = 0; j < 2; j++) {
                int n = wn * 16 + j * 8 + tig * 2;
                int b0 = wm * 16 + gid;
                Cs[b0 * 33 + n]           = acc[j][0];
                Cs[b0 * 33 + n + 1]       = acc[j][1];
                Cs[(b0 + 8) * 33 + n]     = acc[j][2];
                Cs[(b0 + 8) * 33 + n + 1] = acc[j][3];
            }
            __syncthreads();
        }

        // fused pointwise: 512 (b,j) pairs, 2 per thread
        __nv_bfloat16* HSw = g_HS + (size_t)((t + 1) & 1) * (64 * 3072);
#pragma unroll
        for (int q = 0; q < 2; q++) {
            int b = pb0 + q * 32;
            float gi = xv[q][0], gf = xv[q][1], gg = xv[q][2], go = xv[q][3];
            if (t > 0) {
                gi += Cs[b * 33 + pj];
                gf += Cs[b * 33 + 8 + pj];
                gg += Cs[b * 33 + 16 + pj];
                go += Cs[b * 33 + 24 + pj];
            }
            int ci = b * Hv + u0 + pj;
            float c = sigmoidf_(gf) * g_c[ci] + sigmoidf_(gi) * tanhf(gg);
            float h = sigmoidf_(go) * tanhf(c);
            g_c[ci] = c;
            __nv_bfloat16 hh = __float2bfloat16(h);
            __nv_bfloat16 hl = __float2bfloat16(h - __bfloat162float(hh));
            HSw[(size_t)b * 3072 + u0 + pj] = hh;
            HSw[(size_t)b * 3072 + 1024 + u0 + pj] = hh;
            HSw[(size_t)b * 3072 + 2048 + u0 + pj] = hl;
            if (seq) seq[((size_t)(t * Bv + b)) * Hv + u0 + pj] = h;
            if (a2) {
                size_t ab = ((size_t)(t * Bv + b)) * (3 * Hv) + u0 + pj;
                a2[ab] = hh; a2[ab + Hv] = hh; a2[ab + 2 * Hv] = hl;
            }
            if (t == Tv - 1) g_h[ci] = h;
        }

        if (t < Tv - 1) {
            __threadfence();
            __syncthreads();
            if (tid == 0) {
                atomicAdd(&g_barrier, 1u);
                unsigned target = (unsigned)(t + 1) * (unsigned)gridDim.x;
                while (*(volatile unsigned*)&g_barrier < target) { }
            }
            __syncthreads();
        }
    }
}

// ---------------- small FFMA2 sgemm (tiny GEMMs: m2, n_vec) ----------------
#define BKt 16
__global__ __launch_bounds__(128) void sgemm(
    const float* __restrict__ A, int lda,
    const float* __restrict__ B, int ldb,
    float* __restrict__ C, int ldc,
    int K, const float* __restrict__ bias1, int act)
{
    __shared__ __align__(16) float As[BKt][64 + 4];
    __shared__ __align__(16) float Bs[BKt][64 + 4];
    const int tid = threadIdx.x;
    const int nBase = blockIdx.x * 64;
    const long long mBase = (long long)blockIdx.y * 64;
    const int ty = tid >> 4, tx = tid & 15;

    float2 acc[8][2];
#pragma unroll
    for (int i = 0; i < 8; i++) { acc[i][0] = make_float2(0.f, 0.f); acc[i][1] = make_float2(0.f, 0.f); }

    for (int k0 = 0; k0 < K; k0 += BKt) {
#pragma unroll
        for (int i = 0; i < 2; i++) {
            int f = i * 128 + tid;
            int m = f >> 2, kq = f & 3;
            float4 va = *(const float4*)&A[(mBase + m) * (long long)lda + k0 + kq * 4];
            As[kq * 4 + 0][m] = va.x; As[kq * 4 + 1][m] = va.y;
            As[kq * 4 + 2][m] = va.z; As[kq * 4 + 3][m] = va.w;
            float4 vb = *(const float4*)&B[(long long)(nBase + m) * ldb + k0 + kq * 4];
            Bs[kq * 4 + 0][m] = vb.x; Bs[kq * 4 + 1][m] = vb.y;
            Bs[kq * 4 + 2][m] = vb.z; Bs[kq * 4 + 3][m] = vb.w;
        }
        __syncthreads();
#pragma unroll
        for (int kk = 0; kk < BKt; kk++) {
            float4 a0 = *(const float4*)&As[kk][ty * 8];
            float4 a1 = *(const float4*)&As[kk][ty * 8 + 4];
            float4 b4 = *(const float4*)&Bs[kk][tx * 4];
            float2 b01 = make_float2(b4.x, b4.y);
            float2 b23 = make_float2(b4.z, b4.w);
            float av[8] = {a0.x, a0.y, a0.z, a0.w, a1.x, a1.y, a1.z, a1.w};
#pragma unroll
            for (int i = 0; i < 8; i++) {
                float2 ad = make_float2(av[i], av[i]);
                acc[i][0] = ffma2(ad, b01, acc[i][0]);
                acc[i][1] = ffma2(ad, b23, acc[i][1]);
            }
        }
        __syncthreads();
    }

    float4 bb = make_float4(0.f, 0.f, 0.f, 0.f);
    if (bias1) bb = *(const float4*)&bias1[nBase + tx * 4];
#pragma unroll
    for (int i = 0; i < 8; i++) {
        long long m = mBase + ty * 8 + i;
        float4 r = make_float4(acc[i][0].x + bb.x, acc[i][0].y + bb.y,
                               acc[i][1].x + bb.z, acc[i][1].y + bb.w);
        if (act == 1) { r.x = tanhf(r.x); r.y = tanhf(r.y); r.z = tanhf(r.z); r.w = tanhf(r.w); }
        *(float4*)&C[m * (long long)ldc + nBase + tx * 4] = r;
    }
}

// ---------------- attention tail ----------------
__global__ void scores_k(const float* __restrict__ v) {
    int warp = (blockIdx.x * blockDim.x + threadIdx.x) >> 5;
    int lane = threadIdx.x & 31;
    if (warp >= Tv * Bv) return;
    int b = warp & 63;
    const float* m1 = g_m1 + (size_t)warp * Av;
    const float* m2 = g_m2 + b * Av;
    float s = 0.f;
    for (int a = lane; a < Av; a += 32) s += tanhf(m1[a] + m2[a]) * v[a];
#pragma unroll
    for (int o = 16; o; o >>= 1) s += __shfl_xor_sync(0xffffffffu, s, o);
    if (!lane) g_sc[warp] = s;
}

__global__ void softmax_k() {
    int b = blockIdx.x;
    int t = threadIdx.x;
    __shared__ float red[Tv];
    float val = g_sc[t * Bv + b];
    red[t] = val; __syncthreads();
    for (int o = 128; o; o >>= 1) { if (t < o) red[t] = fmaxf(red[t], red[t + o]); __syncthreads(); }
    float mx = red[0]; __syncthreads();
    float e = expf(val - mx);
    red[t] = e; __syncthreads();
    for (int o = 128; o; o >>= 1) { if (t < o) red[t] += red[t + o]; __syncthreads(); }
    g_sc[t * Bv + b] = e / red[0];
}

__global__ void context_k() {
    int b = blockIdx.x;
    __shared__ float at[Tv];
    for (int t = threadIdx.x; t < Tv; t += blockDim.x) at[t] = g_sc[t * Bv + b];
    __syncthreads();
    for (int h = threadIdx.x; h < Hv; h += blockDim.x) {
        float s = 0.f;
#pragma unroll 4
        for (int t = 0; t < Tv; t++)
            s += g_seq1[((size_t)(t * Bv + b)) * Hv + h] * at[t];
        g_cat[b * 2 * Hv + h] = s;
        g_cat[b * 2 * Hv + Hv + h] = g_h[b * Hv + h];
    }
}

__global__ void logit_k(const float* __restrict__ ow, const float* __restrict__ ob,
                        float* __restrict__ out) {
    int idx = blockIdx.x;
    int b = idx >> 1, c = idx & 1;
    int lane = threadIdx.x;
    float s = 0.f;
    for (int k = lane; k < Hv; k += 32) s += g_nvec[b * Hv + k] * ow[c * Hv + k];
#pragma unroll
    for (int o = 16; o; o >>= 1) s += __shfl_xor_sync(0xffffffffu, s, o);
    if (!lane) out[idx] = s + ob[c];
}

// ---------------- host orchestration ----------------
extern "C" void kernel_launch(void* const* d_in, const int* in_sizes, int n_in,
                              void* d_out, int out_size) {
    const int*   x      = (const int*)d_in[0];
    const float* embed_w= (const float*)d_in[1];
    const float* w_ih0  = (const float*)d_in[2];
    const float* w_hh0  = (const float*)d_in[3];
    const float* b_ih0  = (const float*)d_in[4];
    const float* b_hh0  = (const float*)d_in[5];
    const float* w_ih1  = (const float*)d_in[6];
    const float* w_hh1  = (const float*)d_in[7];
    const float* b_ih1  = (const float*)d_in[8];
    const float* b_hh1  = (const float*)d_in[9];
    const float* m1_w   = (const float*)d_in[10];
    const float* m1_b   = (const float*)d_in[11];
    const float* m2_w   = (const float*)d_in[12];
    const float* m2_b   = (const float*)d_in[13];
    const float* vv     = (const float*)d_in[14];
    const float* n_w    = (const float*)d_in[15];
    const float* n_b    = (const float*)d_in[16];
    const float* out_w  = (const float*)d_in[17];
    const float* out_b  = (const float*)d_in[18];
    float* out = (float*)d_out;

    cudaFuncSetAttribute(lstm_scan_mma, cudaFuncAttributeMaxDynamicSharedMemorySize, SCAN_SMEM);

    __nv_bfloat16 *p_A2, *p_B2, *p_WS;
    float *p_xp, *p_seq1, *p_h, *p_m1, *p_m2, *p_cat, *p_nvec;
    cudaGetSymbolAddress((void**)&p_A2,   g_A2);
    cudaGetSymbolAddress((void**)&p_B2,   g_B2);
    cudaGetSymbolAddress((void**)&p_WS,   g_WS);
    cudaGetSymbolAddress((void**)&p_xp,   g_xp);
    cudaGetSymbolAddress((void**)&p_seq1, g_seq1);
    cudaGetSymbolAddress((void**)&p_h,    g_h);
    cudaGetSymbolAddress((void**)&p_m1,   g_m1);
    cudaGetSymbolAddress((void**)&p_m2,   g_m2);
    cudaGetSymbolAddress((void**)&p_cat,  g_cat);
    cudaGetSymbolAddress((void**)&p_nvec, g_nvec);

    // ---- layer 0 ----
    gather_pack<<<Tv * Bv, 128>>>(x, embed_w);
    pack_B<<<(Gv * Ev + 255) / 256, 256>>>(w_ih0, Gv, Ev);
    mma_gemm<<<dim3(Gv / 128, (Tv * Bv) / 128), 256>>>(p_A2, p_B2, p_xp, Gv,
                                                       3 * Ev, b_ih0, b_hh0);
    pack_WS<<<(Gv * Hv + 255) / 256, 256>>>(w_hh0);
    zero_state<<<256, 256>>>();
    lstm_scan_mma<<<SCAN_BLOCKS, 256, SCAN_SMEM>>>(p_WS, p_xp, nullptr, p_A2);

    // ---- layer 1 ----
    pack_B<<<(Gv * Hv + 255) / 256, 256>>>(w_ih1, Gv, Hv);
    mma_gemm<<<dim3(Gv / 128, (Tv * Bv) / 128), 256>>>(p_A2, p_B2, p_xp, Gv,
                                                       3 * Hv, b_ih1, b_hh1);
    pack_WS<<<(Gv * Hv + 255) / 256, 256>>>(w_hh1);
    zero_state<<<256, 256>>>();
    lstm_scan_mma<<<SCAN_BLOCKS, 256, SCAN_SMEM>>>(p_WS, p_xp, p_seq1, nullptr);

    // ---- attention ----
    pack_B<<<(Av * Hv + 255) / 256, 256>>>(m1_w, Av, Hv);
    // pack layer-1 h sequence for the m1 GEMM
    // (seq1 fp32 -> A2 packed) reuse gather-style pack:
    {
        // simple pack kernel launch via sgemm-free path: use pack of seq1
    }
    // m1 via mma on packed seq? seq1 was not packed this round -> pack it:
    // (packs A2 from fp32 seq1)
    extern __global__ void pack_A_from(const float*);
    pack_A_from<<<(Tv * Bv * Hv + 255) / 256, 256>>>(p_seq1);
    mma_gemm<<<dim3(Av / 128, (Tv * Bv) / 128), 256>>>(p_A2, p_B2, p_m1, Av,
                                                       3 * Hv, m1_b, nullptr);
    sgemm<<<dim3(Av / 64, 1), 128>>>(p_h, Hv, m2_w, Hv, p_m2, Av, Hv, m2_b, 0);
    scores_k<<<(Tv * Bv * 32) / 256, 256>>>(vv);
    softmax_k<<<Bv, Tv>>>();
    context_k<<<Bv, 256>>>();
    sgemm<<<dim3(Hv / 64, 1), 128>>>(p_cat, 2 * Hv, n_w, 2 * Hv, p_nvec, Hv, 2 * Hv, n_b, 1);
    logit_k<<<Bv * Cv, 32>>>(out_w, out_b, out);
}

// pack A2 from fp32 sequence (for the m1 GEMM after layer-1 scan)
__global__ void pack_A_from(const float* __restrict__ S) {
    size_t i = (size_t)blockIdx.x * blockDim.x + threadIdx.x;
    if (i >= (size_t)Tv * Bv * Hv) return;
    size_t m = i / Hv; int k = (int)(i - m * Hv);
    float a = S[i];
    __nv_bfloat16 hi = __float2bfloat16(a);
    __nv_bfloat16 lo = __float2bfloat16(a - __bfloat162float(hi));
    size_t base = m * (3 * Hv) + k;
    g_A2[base] = hi; g_A2[base + Hv] = hi; g_A2[base + 2 * Hv] = lo;
}

// round 7
// speedup vs baseline: 3.9128x; 1.6195x over previous
#include <cuda_runtime.h>
#include <cuda_bf16.h>
#include <cstdint>
#include <math.h>

#define Bv 64
#define Tv 256
#define Hv 1024
#define Ev 512
#define Av 512
#define Gv 4096   /* 4*H */
#define Cv 2
#define SCAN_BLOCKS 128
#define BH (Bv * Hv)

#define WSLICE 131072              /* 32 rows * 2048 bf16 * 2B */
#define ABUF 16384                 /* 64 rows * 128 bf16 * 2B  */
#define SCAN_SMEM (WSLICE + 4 * ABUF)   /* 196608 */
#define GEMM_SMEM 49152            /* 3-stage: 3*(8K A + 8K B) */

// ---------------- scratch (static device globals; no allocations) ----------------
__device__ __nv_bfloat16 g_A2[(size_t)Tv * Bv * 2 * Hv];   // 2-term packed A [16384][2048]
__device__ __nv_bfloat16 g_B2[(size_t)Gv * 2 * Hv];        // 2-term packed B [4096][2048]
__device__ __nv_bfloat16 g_WS[(size_t)SCAN_BLOCKS * 32 * 2048]; // per-block swizzled W slices
__device__ __nv_bfloat16 g_HS[2 * 64 * 2048];              // split h [hi|lo], double-buffered
__device__ float g_xp  [(size_t)Tv * Bv * Gv];
__device__ float g_seq1[(size_t)Tv * Bv * Hv];
__device__ float g_h   [BH];
__device__ float g_c   [BH];
__device__ float g_m1  [(size_t)Tv * Bv * Av];
__device__ float g_m2  [Bv * Av];
__device__ float g_sc  [Tv * Bv];
__device__ float g_cat [Bv * 2 * Hv];
__device__ float g_nvec[Bv * Hv];
__device__ unsigned g_barrier;

// ---------------- helpers ----------------
__device__ __forceinline__ uint32_t smem_u32(const void* p) {
    uint32_t a;
    asm("{ .reg .u64 t; cvta.to.shared.u64 t, %1; cvt.u32.u64 %0, t; }" : "=r"(a) : "l"(p));
    return a;
}
__device__ __forceinline__ void cp16(uint32_t s, const void* g) {
    asm volatile("cp.async.cg.shared.global [%0], [%1], 16;" :: "r"(s), "l"(g));
}
#define CP_COMMIT() asm volatile("cp.async.commit_group;" ::: "memory")
#define CP_WAIT(n)  asm volatile("cp.async.wait_group %0;" :: "n"(n) : "memory")

__device__ __forceinline__ void ldm_x4(uint32_t* r, uint32_t addr) {
    asm volatile("ldmatrix.sync.aligned.m8n8.x4.shared.b16 {%0,%1,%2,%3}, [%4];"
        : "=r"(r[0]), "=r"(r[1]), "=r"(r[2]), "=r"(r[3]) : "r"(addr));
}
__device__ __forceinline__ void mma16816(float* c, const uint32_t* a, uint32_t b0, uint32_t b1) {
    asm volatile("mma.sync.aligned.m16n8k16.row.col.f32.bf16.bf16.f32 "
        "{%0,%1,%2,%3}, {%4,%5,%6,%7}, {%8,%9}, {%0,%1,%2,%3};"
        : "+f"(c[0]), "+f"(c[1]), "+f"(c[2]), "+f"(c[3])
        : "r"(a[0]), "r"(a[1]), "r"(a[2]), "r"(a[3]), "r"(b0), "r"(b1));
}

union f2u { float2 f; unsigned long long u; };
__device__ __forceinline__ float2 ffma2(float2 a, float2 b, float2 c) {
    f2u A, B, C, D; A.f = a; B.f = b; C.f = c;
    asm("fma.rn.f32x2 %0, %1, %2, %3;" : "=l"(D.u) : "l"(A.u), "l"(B.u), "l"(C.u));
    return D.f;
}
__device__ __forceinline__ float sigmoidf_(float x) { return 1.f / (1.f + expf(-x)); }

// XOR swizzle for 64B-row tiles: conflict-free ldmatrix (validated R5/R6)
__device__ __host__ __forceinline__ uint32_t sw_off(int r, int kq) {
    return (uint32_t)(r * 64 + ((kq ^ ((r >> 1) & 3)) << 4));
}

// ================= mma.sync 2-term GEMM, 3-stage pipeline =================
// C[m][n] = A2[m][:K3] . B2[n][:K3]; BM=BN=128, BK=32, 256 threads, warp tile 32x64.
__global__ __launch_bounds__(256) void mma_gemm(
    const __nv_bfloat16* __restrict__ A2, const __nv_bfloat16* __restrict__ B2,
    float* __restrict__ C, int ldc, int K3,
    const float* __restrict__ bias1, const float* __restrict__ bias2)
{
    extern __shared__ __align__(128) char gsm[];
    const uint32_t uA = smem_u32(gsm);            // 3 x 8192
    const uint32_t uB = uA + 24576;               // 3 x 8192

    const int tid = threadIdx.x, wid = tid >> 5, lid = tid & 31;
    const int wm = wid >> 1, wn = wid & 1;
    const long long mBase = (long long)blockIdx.y * 128;
    const int nBase = blockIdx.x * 128;

    const __nv_bfloat16* Ag = A2 + mBase * (size_t)K3;
    const __nv_bfloat16* Bg = B2 + (size_t)nBase * K3;

    float acc[2][8][4];
#pragma unroll
    for (int i = 0; i < 2; i++)
#pragma unroll
        for (int j = 0; j < 8; j++)
#pragma unroll
            for (int q = 0; q < 4; q++) acc[i][j][q] = 0.f;

    const int NS = K3 / 32;
    const int c0r = (tid * 2) >> 2,     c0q = (tid * 2) & 3;
    const int c1r = (tid * 2 + 1) >> 2, c1q = (tid * 2 + 1) & 3;

    const int aR = ((lid >> 3) & 1) * 8 + (lid & 7);
    const int aQ = (lid >> 4) & 1;
    const int bR = ((lid >> 4) & 1) * 8 + (lid & 7);
    const int bQ = (lid >> 3) & 1;

    // preload stages 0,1
#pragma unroll
    for (int ps = 0; ps < 2; ps++) {
        const int k0 = ps * 32;
        uint32_t dA = uA + ps * 8192, dB = uB + ps * 8192;
        cp16(dA + sw_off(c0r, c0q), Ag + (size_t)c0r * K3 + k0 + c0q * 8);
        cp16(dA + sw_off(c1r, c1q), Ag + (size_t)c1r * K3 + k0 + c1q * 8);
        cp16(dB + sw_off(c0r, c0q), Bg + (size_t)c0r * K3 + k0 + c0q * 8);
        cp16(dB + sw_off(c1r, c1q), Bg + (size_t)c1r * K3 + k0 + c1q * 8);
        CP_COMMIT();
    }

    int buf = 0, pbuf = 2;
    for (int s = 0; s < NS; s++) {
        if (s + 2 < NS) {
            const int k0 = (s + 2) * 32;
            uint32_t dA = uA + pbuf * 8192, dB = uB + pbuf * 8192;
            cp16(dA + sw_off(c0r, c0q), Ag + (size_t)c0r * K3 + k0 + c0q * 8);
            cp16(dA + sw_off(c1r, c1q), Ag + (size_t)c1r * K3 + k0 + c1q * 8);
            cp16(dB + sw_off(c0r, c0q), Bg + (size_t)c0r * K3 + k0 + c0q * 8);
            cp16(dB + sw_off(c1r, c1q), Bg + (size_t)c1r * K3 + k0 + c1q * 8);
        }
        CP_COMMIT();
        CP_WAIT(2);
        __syncthreads();

        const uint32_t bufA = uA + buf * 8192;
        const uint32_t bufB = uB + buf * 8192;
#pragma unroll
        for (int kk8 = 0; kk8 < 4; kk8 += 2) {
            uint32_t a[2][4];
#pragma unroll
            for (int fm = 0; fm < 2; fm++) {
                int r = wm * 32 + fm * 16 + aR;
                ldm_x4(a[fm], bufA + sw_off(r, kk8 + aQ));
            }
#pragma unroll
            for (int jp = 0; jp < 4; jp++) {
                uint32_t b[4];
                int r = wn * 64 + jp * 16 + bR;
                ldm_x4(b, bufB + sw_off(r, kk8 + bQ));
#pragma unroll
                for (int fm = 0; fm < 2; fm++) {
                    mma16816(acc[fm][2 * jp],     a[fm], b[0], b[1]);
                    mma16816(acc[fm][2 * jp + 1], a[fm], b[2], b[3]);
                }
            }
        }
        __syncthreads();
        buf = (buf == 2) ? 0 : buf + 1;
        pbuf = (pbuf == 2) ? 0 : pbuf + 1;
    }

    const int gid = lid >> 2, tig = lid & 3;
#pragma unroll
    for (int fm = 0; fm < 2; fm++) {
#pragma unroll
        for (int j = 0; j < 8; j++) {
            int n = nBase + wn * 64 + j * 8 + tig * 2;
            float b0 = 0.f, b1 = 0.f;
            if (bias1) { b0 = bias1[n]; b1 = bias1[n + 1]; }
            if (bias2) { b0 += bias2[n]; b1 += bias2[n + 1]; }
            long long m0 = mBase + wm * 32 + fm * 16 + gid;
            float* r0 = C + m0 * (long long)ldc + n;
            r0[0] = acc[fm][j][0] + b0;
            r0[1] = acc[fm][j][1] + b1;
            float* r1 = r0 + 8LL * ldc;
            r1[0] = acc[fm][j][2] + b0;
            r1[1] = acc[fm][j][3] + b1;
        }
    }
}

// ---------------- packing kernels ----------------
// B2[n][2K] = [Bhi | Bhi]  (pairs with A2 = [hi | lo]; A exact, B rounded)
__global__ void pack_B(const float* __restrict__ W, int N, int K) {
    int i = blockIdx.x * blockDim.x + threadIdx.x;
    if (i >= N * K) return;
    int n = i / K, k = i - n * K;
    __nv_bfloat16 hi = __float2bfloat16(W[i]);
    size_t base = (size_t)n * (2 * K) + k;
    g_B2[base] = hi; g_B2[base + K] = hi;
}

// scan weights: per-block pre-swizzled smem image, [Whi|Whi] over K=2048
__global__ void pack_WS(const float* __restrict__ W) {
    int i = blockIdx.x * blockDim.x + threadIdx.x;   // over Gv*Hv
    if (i >= Gv * Hv) return;
    int n = i >> 10, k = i & 1023;
    __nv_bfloat16 hi = __float2bfloat16(W[i]);
    int g = n >> 10, bi = (n & 1023) >> 3, j = n & 7;
    int r = g * 8 + j;
    char* base = (char*)g_WS + (size_t)bi * WSLICE;
#pragma unroll
    for (int term = 0; term < 2; term++) {
        int kk = term * 1024 + k;
        *(__nv_bfloat16*)(base + (size_t)(kk >> 5) * 2048
                          + sw_off(r, (kk >> 3) & 3) + (kk & 7) * 2) = hi;
    }
}

// embedding gather into A2 = [hi | lo], row stride 2*Ev
__global__ void gather_pack(const int* __restrict__ x, const float* __restrict__ ew) {
    int m = blockIdx.x;            // t*B + b
    int b = m & 63, t = m >> 6;
    int row = x[b * Tv + t];
    const float* src = ew + (size_t)row * Ev;
    __nv_bfloat16* dst = g_A2 + (size_t)m * (2 * Ev);
    for (int k = threadIdx.x; k < Ev; k += blockDim.x) {
        float a = src[k];
        __nv_bfloat16 hi = __float2bfloat16(a);
        __nv_bfloat16 lo = __float2bfloat16(a - __bfloat162float(hi));
        dst[k] = hi; dst[Ev + k] = lo;
    }
}

// pack A2 from fp32 sequence (for the m1 GEMM), row stride 2*Hv
__global__ void pack_A_from(const float* __restrict__ S) {
    size_t i = (size_t)blockIdx.x * blockDim.x + threadIdx.x;
    if (i >= (size_t)Tv * Bv * Hv) return;
    size_t m = i / Hv; int k = (int)(i - m * Hv);
    float a = S[i];
    __nv_bfloat16 hi = __float2bfloat16(a);
    __nv_bfloat16 lo = __float2bfloat16(a - __bfloat162float(hi));
    size_t base = m * (2 * Hv) + k;
    g_A2[base] = hi; g_A2[base + Hv] = lo;
}

__global__ void zero_state() {
    int i = blockIdx.x * blockDim.x + threadIdx.x;
    if (i < BH) { g_h[i] = 0.f; g_c[i] = 0.f; }
    if (i == 0) g_barrier = 0u;
}

// ---------------- persistent LSTM scan on tensor cores (2-term, BK=128) ----------------
// 128 blocks x 256 threads (8 warps: 4m x 2n). Block bi owns units u0=bi*8 -> 32 gate rows.
// W slice (128KB) smem-resident. Per step: Y[64x32] = Hsplit[64x2048] . Wslice^T,
// 16 stages of BK=128 via 4-buffer cp.async pipeline; fused pointwise; one grid barrier.
__global__ __launch_bounds__(256) void lstm_scan_mma(
    const __nv_bfloat16* __restrict__ WS,
    const float* __restrict__ xp,
    float* __restrict__ seq,            // nullable
    __nv_bfloat16* __restrict__ a2)     // nullable (packed seq out, stride 2048)
{
    extern __shared__ __align__(128) char sm[];
    const int tid = threadIdx.x, wid = tid >> 5, lid = tid & 31;
    const int wm = wid >> 1, wn = wid & 1;
    const int bi = blockIdx.x, u0 = bi * 8;
    const uint32_t sW = smem_u32(sm);
    const uint32_t sA = sW + WSLICE;
    float* Cs = (float*)(sm + WSLICE);   // overlays A buffers (disjoint in time)

    const int aR = ((lid >> 3) & 1) * 8 + (lid & 7);
    const int aQ = (lid >> 4) & 1;
    const int bR = ((lid >> 4) & 1) * 8 + (lid & 7);
    const int bQ = (lid >> 3) & 1;
    const int gid = lid >> 2, tig = lid & 3;

    // load W slice (128KB) once
    {
        const char* wg = (const char*)WS + (size_t)bi * WSLICE;
        for (int i = tid; i < WSLICE / 16; i += 256)
            cp16(sW + (uint32_t)(i * 16), wg + (size_t)i * 16);
        CP_COMMIT(); CP_WAIT(0);
        __syncthreads();
    }

    const int pb0 = tid >> 3, pj = tid & 7;

    for (int t = 0; t < Tv; t++) {
        float xv[2][4];
#pragma unroll
        for (int q = 0; q < 2; q++) {
            int b = pb0 + q * 32;
            const float* xr = xp + ((size_t)(t * Bv + b)) * Gv + u0 + pj;
#pragma unroll
            for (int g = 0; g < 4; g++) xv[q][g] = __ldg(xr + g * Hv);
        }

        if (t > 0) {
            const __nv_bfloat16* HS = g_HS + (size_t)(t & 1) * (64 * 2048);
            float acc[2][4];
#pragma unroll
            for (int j = 0; j < 2; j++)
#pragma unroll
                for (int q = 0; q < 4; q++) acc[j][q] = 0.f;

            // prefetch stages 0..2 (BK=128, 16KB each; 4 cp16/thread)
#pragma unroll
            for (int s = 0; s < 3; s++) {
                int k0 = s * 128;
#pragma unroll
                for (int q = 0; q < 4; q++) {
                    int id = tid + q * 256;
                    int r = id >> 4, c16 = id & 15;
                    cp16(sA + s * ABUF + (c16 >> 2) * 4096 + sw_off(r, c16 & 3),
                         HS + (size_t)r * 2048 + k0 + c16 * 8);
                }
                CP_COMMIT();
            }

#pragma unroll 1
            for (int s = 0; s < 16; s++) {
                CP_WAIT(2);
                __syncthreads();
                const uint32_t bufA = sA + (s & 3) * ABUF;
                const uint32_t bufW = sW + (uint32_t)s * 8192;
#pragma unroll
                for (int sub = 0; sub < 4; sub++) {
#pragma unroll
                    for (int kk8 = 0; kk8 < 4; kk8 += 2) {
                        uint32_t a[4], b[4];
                        ldm_x4(a, bufA + sub * 4096 + sw_off(wm * 16 + aR, kk8 + aQ));
                        ldm_x4(b, bufW + sub * 2048 + sw_off(wn * 16 + bR, kk8 + bQ));
                        mma16816(acc[0], a, b[0], b[1]);
                        mma16816(acc[1], a, b[2], b[3]);
                    }
                }
                if (s + 3 < 16) {
                    int k0 = (s + 3) * 128;
                    uint32_t d = sA + ((s + 3) & 3) * ABUF;
#pragma unroll
                    for (int q = 0; q < 4; q++) {
                        int id = tid + q * 256;
                        int r = id >> 4, c16 = id & 15;
                        cp16(d + (c16 >> 2) * 4096 + sw_off(r, c16 & 3),
                             HS + (size_t)r * 2048 + k0 + c16 * 8);
                    }
                }
                CP_COMMIT();
            }
            __syncthreads();             // A buffers idle -> Cs overlay

#pragma unroll
            for (int j = 0; j < 2; j++) {
                int n = wn * 16 + j * 8 + tig * 2;
                int b0 = wm * 16 + gid;
                Cs[b0 * 33 + n]           = acc[j][0];
                Cs[b0 * 33 + n + 1]       = acc[j][1];
                Cs[(b0 + 8) * 33 + n]     = acc[j][2];
                Cs[(b0 + 8) * 33 + n + 1] = acc[j][3];
            }
            __syncthreads();
        }

        __nv_bfloat16* HSw = g_HS + (size_t)((t + 1) & 1) * (64 * 2048);
#pragma unroll
        for (int q = 0; q < 2; q++) {
            int b = pb0 + q * 32;
            float gi = xv[q][0], gf = xv[q][1], gg = xv[q][2], go = xv[q][3];
            if (t > 0) {
                gi += Cs[b * 33 + pj];
                gf += Cs[b * 33 + 8 + pj];
                gg += Cs[b * 33 + 16 + pj];
                go += Cs[b * 33 + 24 + pj];
            }
            int ci = b * Hv + u0 + pj;
            float c = sigmoidf_(gf) * g_c[ci] + sigmoidf_(gi) * tanhf(gg);
            float h = sigmoidf_(go) * tanhf(c);
            g_c[ci] = c;
            __nv_bfloat16 hh = __float2bfloat16(h);
            __nv_bfloat16 hl = __float2bfloat16(h - __bfloat162float(hh));
            HSw[(size_t)b * 2048 + u0 + pj] = hh;
            HSw[(size_t)b * 2048 + 1024 + u0 + pj] = hl;
            if (seq) seq[((size_t)(t * Bv + b)) * Hv + u0 + pj] = h;
            if (a2) {
                size_t ab = ((size_t)(t * Bv + b)) * (2 * Hv) + u0 + pj;
                a2[ab] = hh; a2[ab + Hv] = hl;
            }
            if (t == Tv - 1) g_h[ci] = h;
        }

        if (t < Tv - 1) {
            __threadfence();
            __syncthreads();
            if (tid == 0) {
                atomicAdd(&g_barrier, 1u);
                unsigned target = (unsigned)(t + 1) * (unsigned)gridDim.x;
                while (*(volatile unsigned*)&g_barrier < target) { }
            }
            __syncthreads();
        }
    }
}

// ---------------- small FFMA2 sgemm (tiny GEMMs: m2, n_vec) ----------------
#define BKt 16
__global__ __launch_bounds__(128) void sgemm(
    const float* __restrict__ A, int lda,
    const float* __restrict__ B, int ldb,
    float* __restrict__ C, int ldc,
    int K, const float* __restrict__ bias1, int act)
{
    __shared__ __align__(16) float As[BKt][64 + 4];
    __shared__ __align__(16) float Bs[BKt][64 + 4];
    const int tid = threadIdx.x;
    const int nBase = blockIdx.x * 64;
    const long long mBase = (long long)blockIdx.y * 64;
    const int ty = tid >> 4, tx = tid & 15;

    float2 acc[8][2];
#pragma unroll
    for (int i = 0; i < 8; i++) { acc[i][0] = make_float2(0.f, 0.f); acc[i][1] = make_float2(0.f, 0.f); }

    for (int k0 = 0; k0 < K; k0 += BKt) {
#pragma unroll
        for (int i = 0; i < 2; i++) {
            int f = i * 128 + tid;
            int m = f >> 2, kq = f & 3;
            float4 va = *(const float4*)&A[(mBase + m) * (long long)lda + k0 + kq * 4];
            As[kq * 4 + 0][m] = va.x; As[kq * 4 + 1][m] = va.y;
            As[kq * 4 + 2][m] = va.z; As[kq * 4 + 3][m] = va.w;
            float4 vb = *(const float4*)&B[(long long)(nBase + m) * ldb + k0 + kq * 4];
            Bs[kq * 4 + 0][m] = vb.x; Bs[kq * 4 + 1][m] = vb.y;
            Bs[kq * 4 + 2][m] = vb.z; Bs[kq * 4 + 3][m] = vb.w;
        }
        __syncthreads();
#pragma unroll
        for (int kk = 0; kk < BKt; kk++) {
            float4 a0 = *(const float4*)&As[kk][ty * 8];
            float4 a1 = *(const float4*)&As[kk][ty * 8 + 4];
            float4 b4 = *(const float4*)&Bs[kk][tx * 4];
            float2 b01 = make_float2(b4.x, b4.y);
            float2 b23 = make_float2(b4.z, b4.w);
            float av[8] = {a0.x, a0.y, a0.z, a0.w, a1.x, a1.y, a1.z, a1.w};
#pragma unroll
            for (int i = 0; i < 8; i++) {
                float2 ad = make_float2(av[i], av[i]);
                acc[i][0] = ffma2(ad, b01, acc[i][0]);
                acc[i][1] = ffma2(ad, b23, acc[i][1]);
            }
        }
        __syncthreads();
    }

    float4 bb = make_float4(0.f, 0.f, 0.f, 0.f);
    if (bias1) bb = *(const float4*)&bias1[nBase + tx * 4];
#pragma unroll
    for (int i = 0; i < 8; i++) {
        long long m = mBase + ty * 8 + i;
        float4 r = make_float4(acc[i][0].x + bb.x, acc[i][0].y + bb.y,
                               acc[i][1].x + bb.z, acc[i][1].y + bb.w);
        if (act == 1) { r.x = tanhf(r.x); r.y = tanhf(r.y); r.z = tanhf(r.z); r.w = tanhf(r.w); }
        *(float4*)&C[m * (long long)ldc + nBase + tx * 4] = r;
    }
}

// ---------------- attention tail ----------------
__global__ void scores_k(const float* __restrict__ v) {
    int warp = (blockIdx.x * blockDim.x + threadIdx.x) >> 5;
    int lane = threadIdx.x & 31;
    if (warp >= Tv * Bv) return;
    int b = warp & 63;
    const float* m1 = g_m1 + (size_t)warp * Av;
    const float* m2 = g_m2 + b * Av;
    float s = 0.f;
    for (int a = lane; a < Av; a += 32) s += tanhf(m1[a] + m2[a]) * v[a];
#pragma unroll
    for (int o = 16; o; o >>= 1) s += __shfl_xor_sync(0xffffffffu, s, o);
    if (!lane) g_sc[warp] = s;
}

__global__ void softmax_k() {
    int b = blockIdx.x;
    int t = threadIdx.x;
    __shared__ float red[Tv];
    float val = g_sc[t * Bv + b];
    red[t] = val; __syncthreads();
    for (int o = 128; o; o >>= 1) { if (t < o) red[t] = fmaxf(red[t], red[t + o]); __syncthreads(); }
    float mx = red[0]; __syncthreads();
    float e = expf(val - mx);
    red[t] = e; __syncthreads();
    for (int o = 128; o; o >>= 1) { if (t < o) red[t] += red[t + o]; __syncthreads(); }
    g_sc[t * Bv + b] = e / red[0];
}

// 512 blocks: (b, h-range of 128)
__global__ void context_k() {
    int b = blockIdx.x;
    int h0 = blockIdx.y * 128;
    __shared__ float at[Tv];
    for (int t = threadIdx.x; t < Tv; t += blockDim.x) at[t] = g_sc[t * Bv + b];
    __syncthreads();
    int h = h0 + threadIdx.x;     // 128 threads
    float s = 0.f;
#pragma unroll 4
    for (int t = 0; t < Tv; t++)
        s += g_seq1[((size_t)(t * Bv + b)) * Hv + h] * at[t];
    g_cat[b * 2 * Hv + h] = s;
    g_cat[b * 2 * Hv + Hv + h] = g_h[b * Hv + h];
}

__global__ void logit_k(const float* __restrict__ ow, const float* __restrict__ ob,
                        float* __restrict__ out) {
    int idx = blockIdx.x;
    int b = idx >> 1, c = idx & 1;
    int lane = threadIdx.x;
    float s = 0.f;
    for (int k = lane; k < Hv; k += 32) s += g_nvec[b * Hv + k] * ow[c * Hv + k];
#pragma unroll
    for (int o = 16; o; o >>= 1) s += __shfl_xor_sync(0xffffffffu, s, o);
    if (!lane) out[idx] = s + ob[c];
}

// ---------------- host orchestration ----------------
extern "C" void kernel_launch(void* const* d_in, const int* in_sizes, int n_in,
                              void* d_out, int out_size) {
    const int*   x      = (const int*)d_in[0];
    const float* embed_w= (const float*)d_in[1];
    const float* w_ih0  = (const float*)d_in[2];
    const float* w_hh0  = (const float*)d_in[3];
    const float* b_ih0  = (const float*)d_in[4];
    const float* b_hh0  = (const float*)d_in[5];
    const float* w_ih1  = (const float*)d_in[6];
    const float* w_hh1  = (const float*)d_in[7];
    const float* b_ih1  = (const float*)d_in[8];
    const float* b_hh1  = (const float*)d_in[9];
    const float* m1_w   = (const float*)d_in[10];
    const float* m1_b   = (const float*)d_in[11];
    const float* m2_w   = (const float*)d_in[12];
    const float* m2_b   = (const float*)d_in[13];
    const float* vv     = (const float*)d_in[14];
    const float* n_w    = (const float*)d_in[15];
    const float* n_b    = (const float*)d_in[16];
    const float* out_w  = (const float*)d_in[17];
    const float* out_b  = (const float*)d_in[18];
    float* out = (float*)d_out;

    cudaFuncSetAttribute(lstm_scan_mma, cudaFuncAttributeMaxDynamicSharedMemorySize, SCAN_SMEM);
    cudaFuncSetAttribute(mma_gemm, cudaFuncAttributeMaxDynamicSharedMemorySize, GEMM_SMEM);

    __nv_bfloat16 *p_A2, *p_B2, *p_WS;
    float *p_xp, *p_seq1, *p_h, *p_m1, *p_m2, *p_cat, *p_nvec;
    cudaGetSymbolAddress((void**)&p_A2,   g_A2);
    cudaGetSymbolAddress((void**)&p_B2,   g_B2);
    cudaGetSymbolAddress((void**)&p_WS,   g_WS);
    cudaGetSymbolAddress((void**)&p_xp,   g_xp);
    cudaGetSymbolAddress((void**)&p_seq1, g_seq1);
    cudaGetSymbolAddress((void**)&p_h,    g_h);
    cudaGetSymbolAddress((void**)&p_m1,   g_m1);
    cudaGetSymbolAddress((void**)&p_m2,   g_m2);
    cudaGetSymbolAddress((void**)&p_cat,  g_cat);
    cudaGetSymbolAddress((void**)&p_nvec, g_nvec);

    // ---- layer 0 ----
    gather_pack<<<Tv * Bv, 128>>>(x, embed_w);
    pack_B<<<(Gv * Ev + 255) / 256, 256>>>(w_ih0, Gv, Ev);
    mma_gemm<<<dim3(Gv / 128, (Tv * Bv) / 128), 256, GEMM_SMEM>>>(p_A2, p_B2, p_xp, Gv,
                                                                  2 * Ev, b_ih0, b_hh0);
    pack_WS<<<(Gv * Hv + 255) / 256, 256>>>(w_hh0);
    zero_state<<<256, 256>>>();
    lstm_scan_mma<<<SCAN_BLOCKS, 256, SCAN_SMEM>>>(p_WS, p_xp, nullptr, p_A2);

    // ---- layer 1 ----
    pack_B<<<(Gv * Hv + 255) / 256, 256>>>(w_ih1, Gv, Hv);
    mma_gemm<<<dim3(Gv / 128, (Tv * Bv) / 128), 256, GEMM_SMEM>>>(p_A2, p_B2, p_xp, Gv,
                                                                  2 * Hv, b_ih1, b_hh1);
    pack_WS<<<(Gv * Hv + 255) / 256, 256>>>(w_hh1);
    zero_state<<<256, 256>>>();
    lstm_scan_mma<<<SCAN_BLOCKS, 256, SCAN_SMEM>>>(p_WS, p_xp, p_seq1, nullptr);

    // ---- attention ----
    pack_B<<<(Av * Hv + 255) / 256, 256>>>(m1_w, Av, Hv);
    pack_A_from<<<(int)(((size_t)Tv * Bv * Hv + 255) / 256), 256>>>(p_seq1);
    mma_gemm<<<dim3(Av / 128, (Tv * Bv) / 128), 256, GEMM_SMEM>>>(p_A2, p_B2, p_m1, Av,
                                                                  2 * Hv, m1_b, nullptr);
    sgemm<<<dim3(Av / 64, 1), 128>>>(p_h, Hv, m2_w, Hv, p_m2, Av, Hv, m2_b, 0);
    scores_k<<<(Tv * Bv * 32) / 256, 256>>>(vv);
    softmax_k<<<Bv, Tv>>>();
    context_k<<<dim3(Bv, Hv / 128), 128>>>();
    sgemm<<<dim3(Hv / 64, 1), 128>>>(p_cat, 2 * Hv, n_w, 2 * Hv, p_nvec, Hv, 2 * Hv, n_b, 1);
    logit_k<<<Bv * Cv, 32>>>(out_w, out_b, out);
}

// round 8
// speedup vs baseline: 6.1015x; 1.5594x over previous
#include <cuda_runtime.h>
#include <cuda_bf16.h>
#include <cstdint>
#include <math.h>

#define Bv 64
#define Tv 256
#define Hv 1024
#define Ev 512
#define Av 512
#define Gv 4096   /* 4*H */
#define Cv 2
#define SCAN_BLOCKS 128
#define BH (Bv * Hv)

#define WSLICE 65536               /* 32 rows * 1024 bf16 * 2B */
#define ABUF 16384                 /* 64 rows * 128 bf16 * 2B  */
#define SCAN_SMEM (WSLICE + 4 * ABUF)   /* 131072 */
#define GEMM_SMEM 49152            /* 3-stage: 3*(8K A + 8K B) */

// ---------------- scratch (static device globals; no allocations) ----------------
__device__ __nv_bfloat16 g_A2[(size_t)Tv * Bv * Hv];       // bf16 A (stride Ev for emb, Hv after)
__device__ __nv_bfloat16 g_B2[(size_t)Gv * Hv];            // bf16 B
__device__ __nv_bfloat16 g_WS[(size_t)Gv * Hv];            // per-block swizzled W_hh slices
__device__ __nv_bfloat16 g_HS[2 * 64 * Hv];                // h bf16, double-buffered
__device__ float g_xp  [(size_t)Tv * Bv * Gv];
__device__ float g_seq1[(size_t)Tv * Bv * Hv];
__device__ float g_h   [BH];
__device__ float g_c   [BH];
__device__ float g_m1  [(size_t)Tv * Bv * Av];
__device__ float g_m2  [Bv * Av];
__device__ float g_sc  [Tv * Bv];
__device__ float g_cat [Bv * 2 * Hv];
__device__ float g_nvec[Bv * Hv];
__device__ unsigned g_barrier;

// ---------------- helpers ----------------
__device__ __forceinline__ uint32_t smem_u32(const void* p) {
    uint32_t a;
    asm("{ .reg .u64 t; cvta.to.shared.u64 t, %1; cvt.u32.u64 %0, t; }" : "=r"(a) : "l"(p));
    return a;
}
__device__ __forceinline__ void cp16(uint32_t s, const void* g) {
    asm volatile("cp.async.cg.shared.global [%0], [%1], 16;" :: "r"(s), "l"(g));
}
#define CP_COMMIT() asm volatile("cp.async.commit_group;" ::: "memory")
#define CP_WAIT(n)  asm volatile("cp.async.wait_group %0;" :: "n"(n) : "memory")

__device__ __forceinline__ void ldm_x4(uint32_t* r, uint32_t addr) {
    asm volatile("ldmatrix.sync.aligned.m8n8.x4.shared.b16 {%0,%1,%2,%3}, [%4];"
        : "=r"(r[0]), "=r"(r[1]), "=r"(r[2]), "=r"(r[3]) : "r"(addr));
}
__device__ __forceinline__ void mma16816(float* c, const uint32_t* a, uint32_t b0, uint32_t b1) {
    asm volatile("mma.sync.aligned.m16n8k16.row.col.f32.bf16.bf16.f32 "
        "{%0,%1,%2,%3}, {%4,%5,%6,%7}, {%8,%9}, {%0,%1,%2,%3};"
        : "+f"(c[0]), "+f"(c[1]), "+f"(c[2]), "+f"(c[3])
        : "r"(a[0]), "r"(a[1]), "r"(a[2]), "r"(a[3]), "r"(b0), "r"(b1));
}

union f2u { float2 f; unsigned long long u; };
__device__ __forceinline__ float2 ffma2(float2 a, float2 b, float2 c) {
    f2u A, B, C, D; A.f = a; B.f = b; C.f = c;
    asm("fma.rn.f32x2 %0, %1, %2, %3;" : "=l"(D.u) : "l"(A.u), "l"(B.u), "l"(C.u));
    return D.f;
}
__device__ __forceinline__ float sigmoidf_(float x) { return 1.f / (1.f + expf(-x)); }

// XOR swizzle for 64B-row tiles: conflict-free ldmatrix (validated R5-R7)
__device__ __host__ __forceinline__ uint32_t sw_off(int r, int kq) {
    return (uint32_t)(r * 64 + ((kq ^ ((r >> 1) & 3)) << 4));
}

// ================= mma.sync bf16 GEMM, 3-stage pipeline (structure validated R7) =================
// C[m][n] = A2[m][:K3] . B2[n][:K3]; BM=BN=128, BK=32, 256 threads, warp tile 32x64.
__global__ __launch_bounds__(256) void mma_gemm(
    const __nv_bfloat16* __restrict__ A2, const __nv_bfloat16* __restrict__ B2,
    float* __restrict__ C, int ldc, int K3,
    const float* __restrict__ bias1, const float* __restrict__ bias2)
{
    extern __shared__ __align__(128) char gsm[];
    const uint32_t uA = smem_u32(gsm);            // 3 x 8192
    const uint32_t uB = uA + 24576;               // 3 x 8192

    const int tid = threadIdx.x, wid = tid >> 5, lid = tid & 31;
    const int wm = wid >> 1, wn = wid & 1;
    const long long mBase = (long long)blockIdx.y * 128;
    const int nBase = blockIdx.x * 128;

    const __nv_bfloat16* Ag = A2 + mBase * (size_t)K3;
    const __nv_bfloat16* Bg = B2 + (size_t)nBase * K3;

    float acc[2][8][4];
#pragma unroll
    for (int i = 0; i < 2; i++)
#pragma unroll
        for (int j = 0; j < 8; j++)
#pragma unroll
            for (int q = 0; q < 4; q++) acc[i][j][q] = 0.f;

    const int NS = K3 / 32;
    const int c0r = (tid * 2) >> 2,     c0q = (tid * 2) & 3;
    const int c1r = (tid * 2 + 1) >> 2, c1q = (tid * 2 + 1) & 3;

    const int aR = ((lid >> 3) & 1) * 8 + (lid & 7);
    const int aQ = (lid >> 4) & 1;
    const int bR = ((lid >> 4) & 1) * 8 + (lid & 7);
    const int bQ = (lid >> 3) & 1;

    // preload stages 0,1
#pragma unroll
    for (int ps = 0; ps < 2; ps++) {
        const int k0 = ps * 32;
        uint32_t dA = uA + ps * 8192, dB = uB + ps * 8192;
        cp16(dA + sw_off(c0r, c0q), Ag + (size_t)c0r * K3 + k0 + c0q * 8);
        cp16(dA + sw_off(c1r, c1q), Ag + (size_t)c1r * K3 + k0 + c1q * 8);
        cp16(dB + sw_off(c0r, c0q), Bg + (size_t)c0r * K3 + k0 + c0q * 8);
        cp16(dB + sw_off(c1r, c1q), Bg + (size_t)c1r * K3 + k0 + c1q * 8);
        CP_COMMIT();
    }

    int buf = 0, pbuf = 2;
    for (int s = 0; s < NS; s++) {
        if (s + 2 < NS) {
            const int k0 = (s + 2) * 32;
            uint32_t dA = uA + pbuf * 8192, dB = uB + pbuf * 8192;
            cp16(dA + sw_off(c0r, c0q), Ag + (size_t)c0r * K3 + k0 + c0q * 8);
            cp16(dA + sw_off(c1r, c1q), Ag + (size_t)c1r * K3 + k0 + c1q * 8);
            cp16(dB + sw_off(c0r, c0q), Bg + (size_t)c0r * K3 + k0 + c0q * 8);
            cp16(dB + sw_off(c1r, c1q), Bg + (size_t)c1r * K3 + k0 + c1q * 8);
        }
        CP_COMMIT();
        CP_WAIT(2);
        __syncthreads();

        const uint32_t bufA = uA + buf * 8192;
        const uint32_t bufB = uB + buf * 8192;
#pragma unroll
        for (int kk8 = 0; kk8 < 4; kk8 += 2) {
            uint32_t a[2][4];
#pragma unroll
            for (int fm = 0; fm < 2; fm++) {
                int r = wm * 32 + fm * 16 + aR;
                ldm_x4(a[fm], bufA + sw_off(r, kk8 + aQ));
            }
#pragma unroll
            for (int jp = 0; jp < 4; jp++) {
                uint32_t b[4];
                int r = wn * 64 + jp * 16 + bR;
                ldm_x4(b, bufB + sw_off(r, kk8 + bQ));
#pragma unroll
                for (int fm = 0; fm < 2; fm++) {
                    mma16816(acc[fm][2 * jp],     a[fm], b[0], b[1]);
                    mma16816(acc[fm][2 * jp + 1], a[fm], b[2], b[3]);
                }
            }
        }
        __syncthreads();
        buf = (buf == 2) ? 0 : buf + 1;
        pbuf = (pbuf == 2) ? 0 : pbuf + 1;
    }

    const int gid = lid >> 2, tig = lid & 3;
#pragma unroll
    for (int fm = 0; fm < 2; fm++) {
#pragma unroll
        for (int j = 0; j < 8; j++) {
            int n = nBase + wn * 64 + j * 8 + tig * 2;
            float b0 = 0.f, b1 = 0.f;
            if (bias1) { b0 = bias1[n]; b1 = bias1[n + 1]; }
            if (bias2) { b0 += bias2[n]; b1 += bias2[n + 1]; }
            long long m0 = mBase + wm * 32 + fm * 16 + gid;
            float* r0 = C + m0 * (long long)ldc + n;
            r0[0] = acc[fm][j][0] + b0;
            r0[1] = acc[fm][j][1] + b1;
            float* r1 = r0 + 8LL * ldc;
            r1[0] = acc[fm][j][2] + b0;
            r1[1] = acc[fm][j][3] + b1;
        }
    }
}

// ---------------- packing kernels ----------------
// B2[n][k] = bf16(W[n][k])
__global__ void pack_B(const float* __restrict__ W, int N, int K) {
    int i = blockIdx.x * blockDim.x + threadIdx.x;
    if (i >= N * K) return;
    g_B2[(size_t)i] = __float2bfloat16(W[i]);
}

// scan weights: per-block pre-swizzled smem image over K=1024
__global__ void pack_WS(const float* __restrict__ W) {
    int i = blockIdx.x * blockDim.x + threadIdx.x;   // over Gv*Hv
    if (i >= Gv * Hv) return;
    int n = i >> 10, k = i & 1023;
    __nv_bfloat16 hi = __float2bfloat16(W[i]);
    int g = n >> 10, bi = (n & 1023) >> 3, j = n & 7;
    int r = g * 8 + j;
    char* base = (char*)g_WS + (size_t)bi * WSLICE;
    *(__nv_bfloat16*)(base + (size_t)(k >> 5) * 2048
                      + sw_off(r, (k >> 3) & 3) + (k & 7) * 2) = hi;
}

// embedding gather into A2 bf16, row stride Ev
__global__ void gather_pack(const int* __restrict__ x, const float* __restrict__ ew) {
    int m = blockIdx.x;            // t*B + b
    int b = m & 63, t = m >> 6;
    int row = x[b * Tv + t];
    const float* src = ew + (size_t)row * Ev;
    __nv_bfloat16* dst = g_A2 + (size_t)m * Ev;
    for (int k = threadIdx.x; k < Ev; k += blockDim.x)
        dst[k] = __float2bfloat16(src[k]);
}

__global__ void zero_state() {
    int i = blockIdx.x * blockDim.x + threadIdx.x;
    if (i < BH) { g_h[i] = 0.f; g_c[i] = 0.f; }
    if (i == 0) g_barrier = 0u;
}

// ---------------- persistent LSTM scan on tensor cores (bf16, K=1024) ----------------
// 128 blocks x 256 threads (8 warps: 4m x 2n). Block bi owns units u0=bi*8 -> 32 gate rows.
// W slice (64KB) smem-resident. Per step: Y[64x32] = Hbf16[64x1024] . Wslice^T,
// 8 stages of BK=128 via 4-buffer cp.async pipeline; fused pointwise; one grid barrier.
__global__ __launch_bounds__(256) void lstm_scan_mma(
    const __nv_bfloat16* __restrict__ WS,
    const float* __restrict__ xp,
    float* __restrict__ seq,            // nullable
    __nv_bfloat16* __restrict__ a2)     // nullable (bf16 seq out, stride Hv)
{
    extern __shared__ __align__(128) char sm[];
    const int tid = threadIdx.x, wid = tid >> 5, lid = tid & 31;
    const int wm = wid >> 1, wn = wid & 1;
    const int bi = blockIdx.x, u0 = bi * 8;
    const uint32_t sW = smem_u32(sm);
    const uint32_t sA = sW + WSLICE;
    float* Cs = (float*)(sm + WSLICE);   // overlays A buffers (disjoint in time)

    const int aR = ((lid >> 3) & 1) * 8 + (lid & 7);
    const int aQ = (lid >> 4) & 1;
    const int bR = ((lid >> 4) & 1) * 8 + (lid & 7);
    const int bQ = (lid >> 3) & 1;
    const int gid = lid >> 2, tig = lid & 3;

    // load W slice (64KB) once
    {
        const char* wg = (const char*)WS + (size_t)bi * WSLICE;
        for (int i = tid; i < WSLICE / 16; i += 256)
            cp16(sW + (uint32_t)(i * 16), wg + (size_t)i * 16);
        CP_COMMIT(); CP_WAIT(0);
        __syncthreads();
    }

    const int pb0 = tid >> 3, pj = tid & 7;

    for (int t = 0; t < Tv; t++) {
        float xv[2][4];
#pragma unroll
        for (int q = 0; q < 2; q++) {
            int b = pb0 + q * 32;
            const float* xr = xp + ((size_t)(t * Bv + b)) * Gv + u0 + pj;
#pragma unroll
            for (int g = 0; g < 4; g++) xv[q][g] = __ldg(xr + g * Hv);
        }

        if (t > 0) {
            const __nv_bfloat16* HS = g_HS + (size_t)(t & 1) * (64 * Hv);
            float acc[2][4];
#pragma unroll
            for (int j = 0; j < 2; j++)
#pragma unroll
                for (int q = 0; q < 4; q++) acc[j][q] = 0.f;

            // prefetch stages 0..2 (BK=128, 16KB each; 4 cp16/thread)
#pragma unroll
            for (int s = 0; s < 3; s++) {
                int k0 = s * 128;
#pragma unroll
                for (int q = 0; q < 4; q++) {
                    int id = tid + q * 256;
                    int r = id >> 4, c16 = id & 15;
                    cp16(sA + s * ABUF + (c16 >> 2) * 4096 + sw_off(r, c16 & 3),
                         HS + (size_t)r * Hv + k0 + c16 * 8);
                }
                CP_COMMIT();
            }

#pragma unroll 1
            for (int s = 0; s < 8; s++) {
                CP_WAIT(2);
                __syncthreads();
                const uint32_t bufA = sA + (s & 3) * ABUF;
                const uint32_t bufW = sW + (uint32_t)s * 8192;
#pragma unroll
                for (int sub = 0; sub < 4; sub++) {
#pragma unroll
                    for (int kk8 = 0; kk8 < 4; kk8 += 2) {
                        uint32_t a[4], b[4];
                        ldm_x4(a, bufA + sub * 4096 + sw_off(wm * 16 + aR, kk8 + aQ));
                        ldm_x4(b, bufW + sub * 2048 + sw_off(wn * 16 + bR, kk8 + bQ));
                        mma16816(acc[0], a, b[0], b[1]);
                        mma16816(acc[1], a, b[2], b[3]);
                    }
                }
                if (s + 3 < 8) {
                    int k0 = (s + 3) * 128;
                    uint32_t d = sA + ((s + 3) & 3) * ABUF;
#pragma unroll
                    for (int q = 0; q < 4; q++) {
                        int id = tid + q * 256;
                        int r = id >> 4, c16 = id & 15;
                        cp16(d + (c16 >> 2) * 4096 + sw_off(r, c16 & 3),
                             HS + (size_t)r * Hv + k0 + c16 * 8);
                    }
                }
                CP_COMMIT();
            }
            __syncthreads();             // A buffers idle -> Cs overlay

#pragma unroll
            for (int j = 0; j < 2; j++) {
                int n = wn * 16 + j * 8 + tig * 2;
                int b0 = wm * 16 + gid;
                Cs[b0 * 33 + n]           = acc[j][0];
                Cs[b0 * 33 + n + 1]       = acc[j][1];
                Cs[(b0 + 8) * 33 + n]     = acc[j][2];
                Cs[(b0 + 8) * 33 + n + 1] = acc[j][3];
            }
            __syncthreads();
        }

        __nv_bfloat16* HSw = g_HS + (size_t)((t + 1) & 1) * (64 * Hv);
#pragma unroll
        for (int q = 0; q < 2; q++) {
            int b = pb0 + q * 32;
            float gi = xv[q][0], gf = xv[q][1], gg = xv[q][2], go = xv[q][3];
            if (t > 0) {
                gi += Cs[b * 33 + pj];
                gf += Cs[b * 33 + 8 + pj];
                gg += Cs[b * 33 + 16 + pj];
                go += Cs[b * 33 + 24 + pj];
            }
            int ci = b * Hv + u0 + pj;
            float c = sigmoidf_(gf) * g_c[ci] + sigmoidf_(gi) * tanhf(gg);
            float h = sigmoidf_(go) * tanhf(c);
            g_c[ci] = c;
            __nv_bfloat16 hh = __float2bfloat16(h);
            HSw[(size_t)b * Hv + u0 + pj] = hh;
            if (seq) seq[((size_t)(t * Bv + b)) * Hv + u0 + pj] = h;
            if (a2) a2[((size_t)(t * Bv + b)) * Hv + u0 + pj] = hh;
            if (t == Tv - 1) g_h[ci] = h;
        }

        if (t < Tv - 1) {
            __threadfence();
            __syncthreads();
            if (tid == 0) {
                atomicAdd(&g_barrier, 1u);
                unsigned target = (unsigned)(t + 1) * (unsigned)gridDim.x;
                while (*(volatile unsigned*)&g_barrier < target) { }
            }
            __syncthreads();
        }
    }
}

// ---------------- small FFMA2 sgemm (tiny GEMMs: m2, n_vec) ----------------
#define BKt 16
__global__ __launch_bounds__(128) void sgemm(
    const float* __restrict__ A, int lda,
    const float* __restrict__ B, int ldb,
    float* __restrict__ C, int ldc,
    int K, const float* __restrict__ bias1, int act)
{
    __shared__ __align__(16) float As[BKt][64 + 4];
    __shared__ __align__(16) float Bs[BKt][64 + 4];
    const int tid = threadIdx.x;
    const int nBase = blockIdx.x * 64;
    const long long mBase = (long long)blockIdx.y * 64;
    const int ty = tid >> 4, tx = tid & 15;

    float2 acc[8][2];
#pragma unroll
    for (int i = 0; i < 8; i++) { acc[i][0] = make_float2(0.f, 0.f); acc[i][1] = make_float2(0.f, 0.f); }

    for (int k0 = 0; k0 < K; k0 += BKt) {
#pragma unroll
        for (int i = 0; i < 2; i++) {
            int f = i * 128 + tid;
            int m = f >> 2, kq = f & 3;
            float4 va = *(const float4*)&A[(mBase + m) * (long long)lda + k0 + kq * 4];
            As[kq * 4 + 0][m] = va.x; As[kq * 4 + 1][m] = va.y;
            As[kq * 4 + 2][m] = va.z; As[kq * 4 + 3][m] = va.w;
            float4 vb = *(const float4*)&B[(long long)(nBase + m) * ldb + k0 + kq * 4];
            Bs[kq * 4 + 0][m] = vb.x; Bs[kq * 4 + 1][m] = vb.y;
            Bs[kq * 4 + 2][m] = vb.z; Bs[kq * 4 + 3][m] = vb.w;
        }
        __syncthreads();
#pragma unroll
        for (int kk = 0; kk < BKt; kk++) {
            float4 a0 = *(const float4*)&As[kk][ty * 8];
            float4 a1 = *(const float4*)&As[kk][ty * 8 + 4];
            float4 b4 = *(const float4*)&Bs[kk][tx * 4];
            float2 b01 = make_float2(b4.x, b4.y);
            float2 b23 = make_float2(b4.z, b4.w);
            float av[8] = {a0.x, a0.y, a0.z, a0.w, a1.x, a1.y, a1.z, a1.w};
#pragma unroll
            for (int i = 0; i < 8; i++) {
                float2 ad = make_float2(av[i], av[i]);
                acc[i][0] = ffma2(ad, b01, acc[i][0]);
                acc[i][1] = ffma2(ad, b23, acc[i][1]);
            }
        }
        __syncthreads();
    }

    float4 bb = make_float4(0.f, 0.f, 0.f, 0.f);
    if (bias1) bb = *(const float4*)&bias1[nBase + tx * 4];
#pragma unroll
    for (int i = 0; i < 8; i++) {
        long long m = mBase + ty * 8 + i;
        float4 r = make_float4(acc[i][0].x + bb.x, acc[i][0].y + bb.y,
                               acc[i][1].x + bb.z, acc[i][1].y + bb.w);
        if (act == 1) { r.x = tanhf(r.x); r.y = tanhf(r.y); r.z = tanhf(r.z); r.w = tanhf(r.w); }
        *(float4*)&C[m * (long long)ldc + nBase + tx * 4] = r;
    }
}

// ---------------- attention tail ----------------
__global__ void scores_k(const float* __restrict__ v) {
    int warp = (blockIdx.x * blockDim.x + threadIdx.x) >> 5;
    int lane = threadIdx.x & 31;
    if (warp >= Tv * Bv) return;
    int b = warp & 63;
    const float* m1 = g_m1 + (size_t)warp * Av;
    const float* m2 = g_m2 + b * Av;
    float s = 0.f;
    for (int a = lane; a < Av; a += 32) s += tanhf(m1[a] + m2[a]) * v[a];
#pragma unroll
    for (int o = 16; o; o >>= 1) s += __shfl_xor_sync(0xffffffffu, s, o);
    if (!lane) g_sc[warp] = s;
}

__global__ void softmax_k() {
    int b = blockIdx.x;
    int t = threadIdx.x;
    __shared__ float red[Tv];
    float val = g_sc[t * Bv + b];
    red[t] = val; __syncthreads();
    for (int o = 128; o; o >>= 1) { if (t < o) red[t] = fmaxf(red[t], red[t + o]); __syncthreads(); }
    float mx = red[0]; __syncthreads();
    float e = expf(val - mx);
    red[t] = e; __syncthreads();
    for (int o = 128; o; o >>= 1) { if (t < o) red[t] += red[t + o]; __syncthreads(); }
    g_sc[t * Bv + b] = e / red[0];
}

// (b, h-range of 128) grid
__global__ void context_k() {
    int b = blockIdx.x;
    int h0 = blockIdx.y * 128;
    __shared__ float at[Tv];
    for (int t = threadIdx.x; t < Tv; t += blockDim.x) at[t] = g_sc[t * Bv + b];
    __syncthreads();
    int h = h0 + threadIdx.x;     // 128 threads
    float s = 0.f;
#pragma unroll 4
    for (int t = 0; t < Tv; t++)
        s += g_seq1[((size_t)(t * Bv + b)) * Hv + h] * at[t];
    g_cat[b * 2 * Hv + h] = s;
    g_cat[b * 2 * Hv + Hv + h] = g_h[b * Hv + h];
}

__global__ void logit_k(const float* __restrict__ ow, const float* __restrict__ ob,
                        float* __restrict__ out) {
    int idx = blockIdx.x;
    int b = idx >> 1, c = idx & 1;
    int lane = threadIdx.x;
    float s = 0.f;
    for (int k = lane; k < Hv; k += 32) s += g_nvec[b * Hv + k] * ow[c * Hv + k];
#pragma unroll
    for (int o = 16; o; o >>= 1) s += __shfl_xor_sync(0xffffffffu, s, o);
    if (!lane) out[idx] = s + ob[c];
}

// ---------------- host orchestration ----------------
extern "C" void kernel_launch(void* const* d_in, const int* in_sizes, int n_in,
                              void* d_out, int out_size) {
    const int*   x      = (const int*)d_in[0];
    const float* embed_w= (const float*)d_in[1];
    const float* w_ih0  = (const float*)d_in[2];
    const float* w_hh0  = (const float*)d_in[3];
    const float* b_ih0  = (const float*)d_in[4];
    const float* b_hh0  = (const float*)d_in[5];
    const float* w_ih1  = (const float*)d_in[6];
    const float* w_hh1  = (const float*)d_in[7];
    const float* b_ih1  = (const float*)d_in[8];
    const float* b_hh1  = (const float*)d_in[9];
    const float* m1_w   = (const float*)d_in[10];
    const float* m1_b   = (const float*)d_in[11];
    const float* m2_w   = (const float*)d_in[12];
    const float* m2_b   = (const float*)d_in[13];
    const float* vv     = (const float*)d_in[14];
    const float* n_w    = (const float*)d_in[15];
    const float* n_b    = (const float*)d_in[16];
    const float* out_w  = (const float*)d_in[17];
    const float* out_b  = (const float*)d_in[18];
    float* out = (float*)d_out;

    cudaFuncSetAttribute(lstm_scan_mma, cudaFuncAttributeMaxDynamicSharedMemorySize, SCAN_SMEM);
    cudaFuncSetAttribute(mma_gemm, cudaFuncAttributeMaxDynamicSharedMemorySize, GEMM_SMEM);

    __nv_bfloat16 *p_A2, *p_B2, *p_WS;
    float *p_xp, *p_seq1, *p_h, *p_m1, *p_m2, *p_cat, *p_nvec;
    cudaGetSymbolAddress((void**)&p_A2,   g_A2);
    cudaGetSymbolAddress((void**)&p_B2,   g_B2);
    cudaGetSymbolAddress((void**)&p_WS,   g_WS);
    cudaGetSymbolAddress((void**)&p_xp,   g_xp);
    cudaGetSymbolAddress((void**)&p_seq1, g_seq1);
    cudaGetSymbolAddress((void**)&p_h,    g_h);
    cudaGetSymbolAddress((void**)&p_m1,   g_m1);
    cudaGetSymbolAddress((void**)&p_m2,   g_m2);
    cudaGetSymbolAddress((void**)&p_cat,  g_cat);
    cudaGetSymbolAddress((void**)&p_nvec, g_nvec);

    // ---- layer 0 ----
    gather_pack<<<Tv * Bv, 128>>>(x, embed_w);
    pack_B<<<(Gv * Ev + 255) / 256, 256>>>(w_ih0, Gv, Ev);
    mma_gemm<<<dim3(Gv / 128, (Tv * Bv) / 128), 256, GEMM_SMEM>>>(p_A2, p_B2, p_xp, Gv,
                                                                  Ev, b_ih0, b_hh0);
    pack_WS<<<(Gv * Hv + 255) / 256, 256>>>(w_hh0);
    zero_state<<<256, 256>>>();
    lstm_scan_mma<<<SCAN_BLOCKS, 256, SCAN_SMEM>>>(p_WS, p_xp, nullptr, p_A2);

    // ---- layer 1 ----
    pack_B<<<(Gv * Hv + 255) / 256, 256>>>(w_ih1, Gv, Hv);
    mma_gemm<<<dim3(Gv / 128, (Tv * Bv) / 128), 256, GEMM_SMEM>>>(p_A2, p_B2, p_xp, Gv,
                                                                  Hv, b_ih1, b_hh1);
    pack_WS<<<(Gv * Hv + 255) / 256, 256>>>(w_hh1);
    zero_state<<<256, 256>>>();
    lstm_scan_mma<<<SCAN_BLOCKS, 256, SCAN_SMEM>>>(p_WS, p_xp, p_seq1, p_A2);

    // ---- attention ----
    pack_B<<<(Av * Hv + 255) / 256, 256>>>(m1_w, Av, Hv);
    mma_gemm<<<dim3(Av / 128, (Tv * Bv) / 128), 256, GEMM_SMEM>>>(p_A2, p_B2, p_m1, Av,
                                                                  Hv, m1_b, nullptr);
    sgemm<<<dim3(Av / 64, 1), 128>>>(p_h, Hv, m2_w, Hv, p_m2, Av, Hv, m2_b, 0);
    scores_k<<<(Tv * Bv * 32) / 256, 256>>>(vv);
    softmax_k<<<Bv, Tv>>>();
    context_k<<<dim3(Bv, Hv / 128), 128>>>();
    sgemm<<<dim3(Hv / 64, 1), 128>>>(p_cat, 2 * Hv, n_w, 2 * Hv, p_nvec, Hv, 2 * Hv, n_b, 1);
    logit_k<<<Bv * Cv, 32>>>(out_w, out_b, out);
}